// round 13
// baseline (speedup 1.0000x reference)
#include <cuda_runtime.h>
#include <cuda_fp16.h>
#include <math.h>
#include <stdint.h>

#define TT 512
#define BBATCH 4
#define NT 2048
#define DD 768
#define HH 12
#define HDIM 64
#define MM 3072
#define VV 32128
#define LL 6
#define NEGINF -1e10f
#define WSZ ((long)DD * DD)
#define DMM ((long)DD * MM)
#define KV6LD (LL * 1536)   // 9216

// ---------------- scratch ----------------
__device__ float  g_xe[NT * DD];
__device__ float  g_xd[NT * DD];
__device__ __half g_enc[NT * DD];
__device__ __half g_h[NT * DD];
__device__ __half g_qkv[NT * 3 * DD];
__device__ __half g_q[NT * DD];
__device__ __half g_kv6[(long)NT * KV6LD];
__device__ __half g_ao[NT * DD];
__device__ __half g_hid[NT * MM];
__device__ __half g_bias_e[HH * TT * TT];
__device__ __half g_bias_d[HH * TT * TT];
__device__ int    g_lut_e[1023];
__device__ int    g_lut_d[1023];
__device__ int    g_val_e[NT];
__device__ int    g_val_t[NT];
// transposed fp16 weights [N,K]
__device__ __half g_wA_e[LL * 3 * DD * DD];
__device__ __half g_wo_e[LL * DD * DD];
__device__ __half g_wA_s[LL * 3 * DD * DD];
__device__ __half g_wo_s[LL * DD * DD];
__device__ __half g_cqT [LL * DD * DD];
__device__ __half g_ckvT[LL * 2 * DD * DD];
__device__ __half g_coT [LL * DD * DD];
__device__ __half g_wiT_e [LL * DD * MM];
__device__ __half g_wmoT_e[LL * DD * MM];
__device__ __half g_wiT_d [LL * DD * MM];
__device__ __half g_wmoT_d[LL * DD * MM];
__device__ __half g_logT[(long)VV * DD];

// ---------------- helpers ----------------
__device__ __forceinline__ void cp16(unsigned dst, const void* src)
{ asm volatile("cp.async.cg.shared.global [%0], [%1], 16;\n" :: "r"(dst), "l"(src)); }
__device__ __forceinline__ void cp_commit() { asm volatile("cp.async.commit_group;\n"); }
__device__ __forceinline__ void cp_wait1()  { asm volatile("cp.async.wait_group 1;\n"); }
__device__ __forceinline__ void cp_wait0()  { asm volatile("cp.async.wait_group 0;\n"); }

__device__ __forceinline__ unsigned su32(const void* p)
{ return (unsigned)__cvta_generic_to_shared(p); }

__device__ __forceinline__ void ldsm4(unsigned a_, unsigned* a)
{
    asm volatile("ldmatrix.sync.aligned.m8n8.x4.shared.b16 {%0,%1,%2,%3}, [%4];"
                 : "=r"(a[0]), "=r"(a[1]), "=r"(a[2]), "=r"(a[3]) : "r"(a_));
}
__device__ __forceinline__ void ldsm2(unsigned a_, unsigned* b)
{
    asm volatile("ldmatrix.sync.aligned.m8n8.x2.shared.b16 {%0,%1}, [%2];"
                 : "=r"(b[0]), "=r"(b[1]) : "r"(a_));
}
__device__ __forceinline__ void ldsm2t(unsigned a_, unsigned* b)
{
    asm volatile("ldmatrix.sync.aligned.m8n8.x2.trans.shared.b16 {%0,%1}, [%2];"
                 : "=r"(b[0]), "=r"(b[1]) : "r"(a_));
}
__device__ __forceinline__ void mma16(float* c, const unsigned* a, const unsigned* b)
{
    asm volatile("mma.sync.aligned.m16n8k16.row.col.f32.f16.f16.f32 "
                 "{%0,%1,%2,%3}, {%4,%5,%6,%7}, {%8,%9}, {%0,%1,%2,%3};"
                 : "+f"(c[0]), "+f"(c[1]), "+f"(c[2]), "+f"(c[3])
                 : "r"(a[0]), "r"(a[1]), "r"(a[2]), "r"(a[3]), "r"(b[0]), "r"(b[1]));
}

// ---------------- transposes ----------------
__global__ void transpose_b(const float* __restrict__ src, __half* __restrict__ dst,
                            int K, int N, long ss, long ds)
{
    __shared__ float t[32][33];
    const float* S = src + (long)blockIdx.z * ss;
    __half* D = dst + (long)blockIdx.z * ds;
    int k0 = blockIdx.y * 32, n0 = blockIdx.x * 32;
    int tx = threadIdx.x, ty = threadIdx.y;
#pragma unroll
    for (int i = 0; i < 32; i += 8)
        t[ty + i][tx] = S[(long)(k0 + ty + i) * N + n0 + tx];
    __syncthreads();
#pragma unroll
    for (int i = 0; i < 32; i += 8)
        D[(long)(n0 + ty + i) * K + k0 + tx] = __float2half_rn(t[tx][ty + i]);
}

struct P12 { const float* p[12]; };
struct D8  { __half* wAe; __half* woe; __half* wAs; __half* wos;
             __half* cqT; __half* ckvT; __half* coT; };

__global__ void transpose12(P12 srcs, D8 d)
{
    __shared__ float t[32][33];
    const int mat = blockIdx.z, layer = mat / 12, which = mat % 12;
    const float* S = srcs.p[which] + (long)layer * WSZ;
    __half* D;
    if (which < 3)       D = d.wAe + (long)layer * 3 * WSZ + (long)which * WSZ;
    else if (which == 3) D = d.woe + (long)layer * WSZ;
    else if (which < 7)  D = d.wAs + (long)layer * 3 * WSZ + (long)(which - 4) * WSZ;
    else if (which == 7) D = d.wos + (long)layer * WSZ;
    else if (which == 8) D = d.cqT + (long)layer * WSZ;
    else if (which < 11) D = d.ckvT + (long)layer * 2 * WSZ + (long)(which - 9) * WSZ;
    else                 D = d.coT + (long)layer * WSZ;
    int k0 = blockIdx.y * 32, n0 = blockIdx.x * 32;
    int tx = threadIdx.x, ty = threadIdx.y;
#pragma unroll
    for (int i = 0; i < 32; i += 8)
        t[ty + i][tx] = S[(long)(k0 + ty + i) * DD + n0 + tx];
    __syncthreads();
#pragma unroll
    for (int i = 0; i < 32; i += 8)
        D[(long)(n0 + ty + i) * DD + k0 + tx] = __float2half_rn(t[tx][ty + i]);
}

// ---------------- relpos bucket LUT + bias tables ----------------
__global__ void build_lut(int* __restrict__ lE, int* __restrict__ lD)
{
    int i = blockIdx.x * 256 + threadIdx.x;
    if (i >= 1023) return;
    int n = i - 511;
    {
        int ret = (n < 0) ? 16 : 0;
        int na = n < 0 ? -n : n;
        int bk;
        if (na < 8) bk = ret + na;
        else { int v = 8 + (int)(log((double)na / 8.0) / log(16.0) * 8.0); bk = ret + (v < 15 ? v : 15); }
        lE[i] = bk;
    }
    {
        int na = n > 0 ? n : 0;
        int bk;
        if (na < 16) bk = na;
        else { int v = 16 + (int)(log((double)na / 16.0) / log(8.0) * 16.0); bk = (v < 31 ? v : 31); }
        lD[i] = bk;
    }
}

__global__ void build_bias_h(const float* __restrict__ rel, const int* __restrict__ lut,
                             __half* __restrict__ bias)
{
    int idx = blockIdx.x * 256 + threadIdx.x;
    int q = idx / TT, s = idx % TT;
    int bk = lut[q - s + 511];
#pragma unroll
    for (int h = 0; h < HH; h++)
        bias[(long)h * TT * TT + idx] = __float2half_rn(rel[h * 32 + bk]);
}

// ---------------- tile loaders ----------------
__device__ __forceinline__ void load_tileH128(unsigned sbase, const __half* P,
                                              int row0, int k0, int ld, int tid)
{
#pragma unroll
    for (int j = 0; j < 8; j++) {
        int c = tid + 128 * j, m = c >> 3, kc = c & 7;
        cp16(sbase + ((m * 8 + (kc ^ (m & 7))) << 4),
             P + (long)(row0 + m) * ld + k0 + kc * 8);
    }
}
__device__ __forceinline__ void load_tileH256(unsigned sbase, const __half* P,
                                              int row0, int k0, int ld, int tid)
{
#pragma unroll
    for (int j = 0; j < 4; j++) {
        int c = tid + 256 * j, m = c >> 3, kc = c & 7;
        cp16(sbase + ((m * 8 + (kc ^ (m & 7))) << 4),
             P + (long)(row0 + m) * ld + k0 + kc * 8);
    }
}
// 256 threads: 64 rows x 64 halves
__device__ __forceinline__ void load_tileH64(unsigned sbase, const __half* P,
                                             int row0, int k0, int ld, int tid)
{
#pragma unroll
    for (int j = 0; j < 2; j++) {
        int c = tid + 256 * j, m = c >> 3, kc = c & 7;
        cp16(sbase + ((m * 8 + (kc ^ (m & 7))) << 4),
             P + (long)(row0 + m) * ld + k0 + kc * 8);
    }
}

// ---------------- fp16 NT GEMM, 4 warps / 64x64 warp tiles (big grids) ----------------
template<bool ACC, bool RELU, bool OUTH>
__global__ __launch_bounds__(128) void gemm_h(
    const __half* __restrict__ A, const __half* __restrict__ Bt, void* __restrict__ Cv,
    int K, int lda, int ldb, int ldc)
{
    extern __shared__ char smc[];
    const unsigned asb = su32(smc);
    const unsigned bsb = asb + 32768;
    constexpr int STG = 16384;

    const int tid = threadIdx.x, lane = tid & 31, warp = tid >> 5;
    const int mw = (warp & 1) * 64, nw = (warp >> 1) * 64;
    const int m0 = blockIdx.y * 128, n0 = blockIdx.x * 128;

    float acc[4][8][4];
#pragma unroll
    for (int i = 0; i < 4; i++)
#pragma unroll
        for (int j = 0; j < 8; j++)
#pragma unroll
            for (int q = 0; q < 4; q++) acc[i][j][q] = 0.f;

    const int nk = K >> 6;
    load_tileH128(asb, A, m0, 0, lda, tid);
    load_tileH128(bsb, Bt, n0, 0, ldb, tid);
    cp_commit();

    for (int kt = 0; kt < nk; kt++) {
        const int st = kt & 1;
        if (kt + 1 < nk) {
            load_tileH128(asb + (st ^ 1) * STG, A, m0, (kt + 1) << 6, lda, tid);
            load_tileH128(bsb + (st ^ 1) * STG, Bt, n0, (kt + 1) << 6, ldb, tid);
        }
        cp_commit();
        cp_wait1();
        __syncthreads();

        const unsigned ab = asb + st * STG;
        const unsigned bb = bsb + st * STG;
#pragma unroll
        for (int kk = 0; kk < 64; kk += 16) {
            unsigned a[4][4];
#pragma unroll
            for (int i = 0; i < 4; i++) {
                int r = mw + 16 * i + (lane & 15);
                int ch = (kk >> 3) + (lane >> 4);
                ldsm4(ab + ((r * 8 + (ch ^ (r & 7))) << 4), a[i]);
            }
            unsigned bf[8][2];
#pragma unroll
            for (int jj = 0; jj < 4; jj++) {
                unsigned t4[4];
                int r = nw + 16 * jj + ((lane >> 4) << 3) + (lane & 7);
                int ch = (kk >> 3) + ((lane >> 3) & 1);
                ldsm4(bb + ((r * 8 + (ch ^ (r & 7))) << 4), t4);
                bf[2 * jj][0] = t4[0]; bf[2 * jj][1] = t4[1];
                bf[2 * jj + 1][0] = t4[2]; bf[2 * jj + 1][1] = t4[3];
            }
#pragma unroll
            for (int i = 0; i < 4; i++)
#pragma unroll
                for (int j = 0; j < 8; j++) mma16(acc[i][j], a[i], bf[j]);
        }
        __syncthreads();
    }

#pragma unroll
    for (int i = 0; i < 4; i++) {
        int r = m0 + mw + 16 * i + (lane >> 2);
#pragma unroll
        for (int j = 0; j < 8; j++) {
            int cn = n0 + nw + 8 * j + ((lane & 3) << 1);
            float2 v0 = make_float2(acc[i][j][0], acc[i][j][1]);
            float2 v1 = make_float2(acc[i][j][2], acc[i][j][3]);
            if (RELU) {
                v0.x = fmaxf(v0.x, 0.f); v0.y = fmaxf(v0.y, 0.f);
                v1.x = fmaxf(v1.x, 0.f); v1.y = fmaxf(v1.y, 0.f);
            }
            if (OUTH) {
                __half* C = (__half*)Cv;
                *(__half2*)(C + (long)r * ldc + cn)       = __floats2half2_rn(v0.x, v0.y);
                *(__half2*)(C + (long)(r + 8) * ldc + cn) = __floats2half2_rn(v1.x, v1.y);
            } else {
                float* C = (float*)Cv;
                float2* p0 = (float2*)(C + (long)r * ldc + cn);
                float2* p1 = (float2*)(C + (long)(r + 8) * ldc + cn);
                if (ACC) {
                    float2 o0 = *p0, o1 = *p1;
                    v0.x += o0.x; v0.y += o0.y; v1.x += o1.x; v1.y += o1.y;
                }
                *p0 = v0; *p1 = v1;
            }
        }
    }
}

// ------ fp16 NT GEMM, 8 warps, 64-row M-tile (small-N latency-bound GEMMs) ------
// warp tile 32x32; grid (N/128, M/64); smem 48KB -> 4 CTAs/SM
template<bool ACC, bool RELU, bool OUTH>
__global__ __launch_bounds__(256) void gemm_m64(
    const __half* __restrict__ A, const __half* __restrict__ Bt, void* __restrict__ Cv,
    int K, int lda, int ldb, int ldc)
{
    extern __shared__ char smc[];
    const unsigned asb = su32(smc);
    const unsigned bsb = asb + 16384;               // A: 2 stages x 8KB
    constexpr int STGA = 8192, STGB = 16384;

    const int tid = threadIdx.x, lane = tid & 31, warp = tid >> 5;
    const int mw = (warp & 1) * 32, nw = (warp >> 1) * 32;
    const int m0 = blockIdx.y * 64, n0 = blockIdx.x * 128;

    float acc[2][4][4];
#pragma unroll
    for (int i = 0; i < 2; i++)
#pragma unroll
        for (int j = 0; j < 4; j++)
#pragma unroll
            for (int q = 0; q < 4; q++) acc[i][j][q] = 0.f;

    const int nk = K >> 6;
    load_tileH64(asb, A, m0, 0, lda, tid);
    load_tileH256(bsb, Bt, n0, 0, ldb, tid);
    cp_commit();

    for (int kt = 0; kt < nk; kt++) {
        const int st = kt & 1;
        if (kt + 1 < nk) {
            load_tileH64(asb + (st ^ 1) * STGA, A, m0, (kt + 1) << 6, lda, tid);
            load_tileH256(bsb + (st ^ 1) * STGB, Bt, n0, (kt + 1) << 6, ldb, tid);
        }
        cp_commit();
        cp_wait1();
        __syncthreads();

        const unsigned ab = asb + st * STGA;
        const unsigned bb = bsb + st * STGB;
#pragma unroll
        for (int kk = 0; kk < 64; kk += 16) {
            unsigned a[2][4];
#pragma unroll
            for (int i = 0; i < 2; i++) {
                int r = mw + 16 * i + (lane & 15);
                int ch = (kk >> 3) + (lane >> 4);
                ldsm4(ab + ((r * 8 + (ch ^ (r & 7))) << 4), a[i]);
            }
            unsigned bf[4][2];
#pragma unroll
            for (int j = 0; j < 4; j++) {
                int r = nw + 8 * j + (lane & 7);
                int ch = (kk >> 3) + ((lane >> 3) & 1);
                ldsm2(bb + ((r * 8 + (ch ^ (r & 7))) << 4), bf[j]);
            }
#pragma unroll
            for (int i = 0; i < 2; i++)
#pragma unroll
                for (int j = 0; j < 4; j++) mma16(acc[i][j], a[i], bf[j]);
        }
        __syncthreads();
    }

#pragma unroll
    for (int i = 0; i < 2; i++) {
        int r = m0 + mw + 16 * i + (lane >> 2);
#pragma unroll
        for (int j = 0; j < 4; j++) {
            int cn = n0 + nw + 8 * j + ((lane & 3) << 1);
            float2 v0 = make_float2(acc[i][j][0], acc[i][j][1]);
            float2 v1 = make_float2(acc[i][j][2], acc[i][j][3]);
            if (RELU) {
                v0.x = fmaxf(v0.x, 0.f); v0.y = fmaxf(v0.y, 0.f);
                v1.x = fmaxf(v1.x, 0.f); v1.y = fmaxf(v1.y, 0.f);
            }
            if (OUTH) {
                __half* C = (__half*)Cv;
                *(__half2*)(C + (long)r * ldc + cn)       = __floats2half2_rn(v0.x, v0.y);
                *(__half2*)(C + (long)(r + 8) * ldc + cn) = __floats2half2_rn(v1.x, v1.y);
            } else {
                float* C = (float*)Cv;
                float2* p0 = (float2*)(C + (long)r * ldc + cn);
                float2* p1 = (float2*)(C + (long)(r + 8) * ldc + cn);
                if (ACC) {
                    float2 o0 = *p0, o1 = *p1;
                    v0.x += o0.x; v0.y += o0.y; v1.x += o1.x; v1.y += o1.y;
                }
                *p0 = v0; *p1 = v1;
            }
        }
    }
}

// ================= fused flash attention (fp16 operands, half bias) =================
#define BQ   0
#define BKT  16384
#define BV   49152
#define BP   65536
#define BRED 98304
#define BVK  100352
#define BVQ  102400
#define FASMEM 104448

__global__ __launch_bounds__(256) void flash_attn(
    const __half* __restrict__ Q, int ldq,
    const __half* __restrict__ K, int ldk,
    const __half* __restrict__ V, int ldv,
    const __half* __restrict__ bias,
    const int* __restrict__ validQ, const int* __restrict__ validK,
    int causal, __half* __restrict__ O)
{
    extern __shared__ char smc[];
    float* smf = (float*)smc;
    int* smi = (int*)smc;
    __shared__ int s_anyinvalid;
    const unsigned sb = su32(smc);
    const int tid = threadIdx.x, lane = tid & 31, warp = tid >> 5;
    const int mw = (warp & 3) * 32;
    const int nwid = warp >> 2;
    const int nw = nwid * 64;
    const int nhd = nwid * 32;
    const int q0 = blockIdx.x * 128;
    const int z = blockIdx.y, b = z / HH, h = z % HH;
    const __half* Qp = Q + (long)b * TT * ldq + h * HDIM;
    const __half* Kp = K + (long)b * TT * ldk + h * HDIM;
    const __half* Vp = V + (long)b * TT * ldv + h * HDIM;
    const __half* biasH = bias ? bias + (long)h * TT * TT : nullptr;
    const int nt = TT / 128;

    auto loadQ = [&]() {
#pragma unroll
        for (int j = 0; j < 4; j++) {
            int c = tid + 256 * j, m = c >> 3, kc = c & 7;
            cp16(sb + BQ + ((m * 8 + (kc ^ (m & 7))) << 4),
                 Qp + (long)(q0 + m) * ldq + kc * 8);
        }
    };
    auto loadK = [&](int buf, int st) {
        int s0 = st * 128;
#pragma unroll
        for (int j = 0; j < 4; j++) {
            int c = tid + 256 * j, m = c >> 3, kc = c & 7;
            cp16(sb + BKT + buf * 16384 + ((m * 8 + (kc ^ (m & 7))) << 4),
                 Kp + (long)(s0 + m) * ldk + kc * 8);
        }
    };
    auto loadV = [&](int st) {
        int s0 = st * 128;
#pragma unroll
        for (int j = 0; j < 4; j++) {
            int c = tid + 256 * j, k = c >> 3, nc = c & 7;
            cp16(sb + BV + ((k * 8 + (nc ^ (k & 7))) << 4),
                 Vp + (long)(s0 + k) * ldv + nc * 8);
        }
    };

    loadQ(); loadK(0, 0); cp_commit();
    loadV(0); cp_commit();
    loadK(1, 1); cp_commit();

    smi[(BVK >> 2) + tid] = validK[b * TT + tid];
    smi[(BVK >> 2) + 256 + tid] = validK[b * TT + 256 + tid];
    smi[(BVQ >> 2) + tid] = validQ[b * TT + tid];
    smi[(BVQ >> 2) + 256 + tid] = validQ[b * TT + 256 + tid];
    if (tid == 0) s_anyinvalid = 0;

    cp_wait1();
    __syncthreads();

    int nt_eff = nt;
    if (causal) {
        if (tid < 128 && smi[(BVQ >> 2) + q0 + tid] == 0) s_anyinvalid = 1;
        __syncthreads();
        if (!s_anyinvalid) nt_eff = blockIdx.x + 1;
        __syncthreads();
    }

    float m_run[2][2], s_run[2][2], oacc[2][4][4];
#pragma unroll
    for (int i = 0; i < 2; i++)
#pragma unroll
        for (int rr = 0; rr < 2; rr++) { m_run[i][rr] = -3.0e38f; s_run[i][rr] = 0.f; }
#pragma unroll
    for (int i = 0; i < 2; i++)
#pragma unroll
        for (int j = 0; j < 4; j++)
#pragma unroll
            for (int q = 0; q < 4; q++) oacc[i][j][q] = 0.f;

    for (int t = 0; t < nt_eff; t++) {
        if (t >= 1) {
            loadV(t); cp_commit();
            if (t + 1 < nt_eff) { loadK((t + 1) & 1, t + 1); cp_commit(); }
        }
        const int s0 = t * 128;

        float acc[2][8][4];
#pragma unroll
        for (int i = 0; i < 2; i++)
#pragma unroll
            for (int j = 0; j < 8; j++)
#pragma unroll
                for (int q = 0; q < 4; q++) acc[i][j][q] = 0.f;

        const unsigned kb = sb + BKT + (t & 1) * 16384;
#pragma unroll
        for (int kk = 0; kk < 64; kk += 16) {
            unsigned a[2][4];
#pragma unroll
            for (int i = 0; i < 2; i++) {
                int r = mw + 16 * i + (lane & 15);
                int ch = (kk >> 3) + (lane >> 4);
                ldsm4(sb + BQ + ((r * 8 + (ch ^ (r & 7))) << 4), a[i]);
            }
            unsigned bf[8][2];
#pragma unroll
            for (int j = 0; j < 8; j++) {
                int r = nw + 8 * j + (lane & 7);
                int ch = (kk >> 3) + ((lane >> 3) & 1);
                ldsm2(kb + ((r * 8 + (ch ^ (r & 7))) << 4), bf[j]);
            }
#pragma unroll
            for (int i = 0; i < 2; i++)
#pragma unroll
                for (int j = 0; j < 8; j++) mma16(acc[i][j], a[i], bf[j]);
        }

        // bias + mask
#pragma unroll
        for (int i = 0; i < 2; i++)
#pragma unroll
            for (int rr = 0; rr < 2; rr++) {
                int Rl = mw + 16 * i + 8 * rr + (lane >> 2);
                int q = q0 + Rl;
                int vq = smi[(BVQ >> 2) + q];
#pragma unroll
                for (int j = 0; j < 8; j++) {
                    int Cl = nw + 8 * j + 2 * (lane & 3);
                    int s = s0 + Cl;
                    float b0 = 0.f, b1 = 0.f;
                    if (biasH) {
                        __half2 bb = *(const __half2*)(biasH + (long)q * TT + s);
                        b0 = __half2float(__low2half(bb));
                        b1 = __half2float(__high2half(bb));
                    }
                    int2 vk = *(const int2*)(smi + (BVK >> 2) + s);
                    float v0 = acc[i][j][2 * rr + 0] + b0;
                    float v1 = acc[i][j][2 * rr + 1] + b1;
                    bool m0 = vq && vk.x && (!causal || s <= q);
                    bool m1 = vq && vk.y && (!causal || s + 1 <= q);
                    acc[i][j][2 * rr + 0] = m0 ? v0 : NEGINF;
                    acc[i][j][2 * rr + 1] = m1 ? v1 : NEGINF;
                }
            }

        // row max
        float mp[2][2];
#pragma unroll
        for (int i = 0; i < 2; i++)
#pragma unroll
            for (int rr = 0; rr < 2; rr++) {
                float m = -3.4e38f;
#pragma unroll
                for (int j = 0; j < 8; j++)
                    m = fmaxf(m, fmaxf(acc[i][j][2 * rr], acc[i][j][2 * rr + 1]));
                mp[i][rr] = m;
            }
#pragma unroll
        for (int o = 1; o <= 2; o <<= 1)
#pragma unroll
            for (int i = 0; i < 2; i++)
#pragma unroll
                for (int rr = 0; rr < 2; rr++)
                    mp[i][rr] = fmaxf(mp[i][rr], __shfl_xor_sync(0xffffffffu, mp[i][rr], o));
        if ((lane & 3) == 0) {
#pragma unroll
            for (int i = 0; i < 2; i++)
#pragma unroll
                for (int rr = 0; rr < 2; rr++) {
                    int Rl = mw + 16 * i + 8 * rr + (lane >> 2);
                    smf[(BRED >> 2) + Rl * 2 + nwid] = mp[i][rr];
                }
        }
        __syncthreads();

        float mnew[2][2], scl[2][2];
#pragma unroll
        for (int i = 0; i < 2; i++)
#pragma unroll
            for (int rr = 0; rr < 2; rr++) {
                int Rl = mw + 16 * i + 8 * rr + (lane >> 2);
                float mt = fmaxf(smf[(BRED >> 2) + Rl * 2], smf[(BRED >> 2) + Rl * 2 + 1]);
                float mn = fmaxf(m_run[i][rr], mt);
                scl[i][rr] = __expf(m_run[i][rr] - mn);
                m_run[i][rr] = mn;
                mnew[i][rr] = mn;
            }

        // p = exp(s-m), stage P (fp16), partial sums
        float sp[2][2] = {{0.f, 0.f}, {0.f, 0.f}};
#pragma unroll
        for (int i = 0; i < 2; i++)
#pragma unroll
            for (int rr = 0; rr < 2; rr++) {
                int Rl = mw + 16 * i + 8 * rr + (lane >> 2);
#pragma unroll
                for (int j = 0; j < 8; j++) {
                    float p0 = __expf(acc[i][j][2 * rr + 0] - mnew[i][rr]);
                    float p1 = __expf(acc[i][j][2 * rr + 1] - mnew[i][rr]);
                    sp[i][rr] += p0 + p1;
                    int Cl = nw + 8 * j + 2 * (lane & 3);
                    int nc = Cl >> 3;
                    *(__half2*)(smc + BP + Rl * 256 + ((nc ^ (Rl & 7)) << 4) + (Cl & 7) * 2) =
                        __floats2half2_rn(p0, p1);
                }
            }
#pragma unroll
        for (int o = 1; o <= 2; o <<= 1)
#pragma unroll
            for (int i = 0; i < 2; i++)
#pragma unroll
                for (int rr = 0; rr < 2; rr++)
                    sp[i][rr] += __shfl_xor_sync(0xffffffffu, sp[i][rr], o);
        if ((lane & 3) == 0) {
#pragma unroll
            for (int i = 0; i < 2; i++)
#pragma unroll
                for (int rr = 0; rr < 2; rr++) {
                    int Rl = mw + 16 * i + 8 * rr + (lane >> 2);
                    smf[(BRED >> 2) + 256 + Rl * 2 + nwid] = sp[i][rr];
                }
        }
        if (t + 1 < nt_eff) cp_wait1(); else cp_wait0();
        __syncthreads();

#pragma unroll
        for (int i = 0; i < 2; i++)
#pragma unroll
            for (int rr = 0; rr < 2; rr++) {
                int Rl = mw + 16 * i + 8 * rr + (lane >> 2);
                float st = smf[(BRED >> 2) + 256 + Rl * 2] + smf[(BRED >> 2) + 256 + Rl * 2 + 1];
                s_run[i][rr] = s_run[i][rr] * scl[i][rr] + st;
            }
#pragma unroll
        for (int i = 0; i < 2; i++)
#pragma unroll
            for (int j = 0; j < 4; j++) {
                oacc[i][j][0] *= scl[i][0]; oacc[i][j][1] *= scl[i][0];
                oacc[i][j][2] *= scl[i][1]; oacc[i][j][3] *= scl[i][1];
            }

        // PV
#pragma unroll
        for (int kk = 0; kk < 128; kk += 16) {
            unsigned a[2][4];
#pragma unroll
            for (int i = 0; i < 2; i++) {
                int r = mw + 16 * i + (lane & 15);
                int ch = (kk >> 3) + (lane >> 4);
                ldsm4(sb + BP + ((r * 16 + (ch ^ (r & 7))) << 4), a[i]);
            }
            unsigned bf[4][2];
#pragma unroll
            for (int j = 0; j < 4; j++) {
                int n0c = (nhd + 8 * j) >> 3;
                int r = kk + (lane & 7) + ((lane >> 3) & 1) * 8;
                ldsm2t(sb + BV + ((r * 8 + (n0c ^ (r & 7))) << 4), bf[j]);
            }
#pragma unroll
            for (int i = 0; i < 2; i++)
#pragma unroll
                for (int j = 0; j < 4; j++) mma16(oacc[i][j], a[i], bf[j]);
        }

        if (t + 1 < nt_eff) { cp_wait0(); __syncthreads(); }
    }

    __half* Op = O + (long)b * TT * DD + h * HDIM;
#pragma unroll
    for (int i = 0; i < 2; i++)
#pragma unroll
        for (int rr = 0; rr < 2; rr++) {
            int Rl = mw + 16 * i + 8 * rr + (lane >> 2);
            float inv = 1.0f / s_run[i][rr];
#pragma unroll
            for (int j = 0; j < 4; j++) {
                int cn = nhd + 8 * j + 2 * (lane & 3);
                *(__half2*)(Op + (long)(q0 + Rl) * DD + cn) =
                    __floats2half2_rn(oacc[i][j][2 * rr + 0] * inv,
                                      oacc[i][j][2 * rr + 1] * inv);
            }
        }
}

// ---------------- elementwise ----------------
__global__ __launch_bounds__(192) void rmsnorm_k(const float* __restrict__ X,
                                                 const float* __restrict__ scale,
                                                 __half* __restrict__ O)
{
    const int row = blockIdx.x, tid = threadIdx.x;
    float4 v = ((const float4*)(X + (long)row * DD))[tid];
    float s = v.x * v.x + v.y * v.y + v.z * v.z + v.w * v.w;
#pragma unroll
    for (int o = 16; o > 0; o >>= 1) s += __shfl_xor_sync(0xffffffffu, s, o);
    __shared__ float red[6];
    if ((tid & 31) == 0) red[tid >> 5] = s;
    __syncthreads();
    float tot = red[0] + red[1] + red[2] + red[3] + red[4] + red[5];
    float r = 1.0f / sqrtf(tot / (float)DD + 1e-6f);
    float4 sc = ((const float4*)scale)[tid];
    __half2* op = (__half2*)(O + (long)row * DD);
    op[2 * tid]     = __floats2half2_rn(v.x * r * sc.x, v.y * r * sc.y);
    op[2 * tid + 1] = __floats2half2_rn(v.z * r * sc.z, v.w * r * sc.w);
}

__global__ void embed_k(const int* __restrict__ tok, const float* __restrict__ emb,
                        float* __restrict__ O)
{
    int t = blockIdx.x, token = tok[t];
    const float* e = emb + (size_t)token * DD;
    for (int d = threadIdx.x; d < DD; d += 256) O[(size_t)t * DD + d] = e[d];
}

__global__ void valid2_k(const int* __restrict__ tokA, const int* __restrict__ tokB,
                         int* __restrict__ vA, int* __restrict__ vB)
{
    int i = blockIdx.x * blockDim.x + threadIdx.x;
    if (i < NT) vA[i] = tokA[i] > 0 ? 1 : 0;
    else { int j = i - NT; vB[j] = tokB[j] > 0 ? 1 : 0; }
}

// ---------------- host ----------------
#define SMEM_G 65536
#define SMEM_M64 49152

static void set_attrs()
{
    cudaFuncSetAttribute(gemm_h<false, false, true >, cudaFuncAttributeMaxDynamicSharedMemorySize, SMEM_G);
    cudaFuncSetAttribute(gemm_h<false, true,  true >, cudaFuncAttributeMaxDynamicSharedMemorySize, SMEM_G);
    cudaFuncSetAttribute(gemm_h<false, false, false>, cudaFuncAttributeMaxDynamicSharedMemorySize, SMEM_G);
    cudaFuncSetAttribute(gemm_m64<true,  false, false>, cudaFuncAttributeMaxDynamicSharedMemorySize, SMEM_M64);
    cudaFuncSetAttribute(gemm_m64<false, false, true >, cudaFuncAttributeMaxDynamicSharedMemorySize, SMEM_M64);
    cudaFuncSetAttribute(flash_attn, cudaFuncAttributeMaxDynamicSharedMemorySize, FASMEM);
}

extern "C" void kernel_launch(void* const* d_in, const int* in_sizes, int n_in,
                              void* d_out, int out_size)
{
    const float* emb      = (const float*)d_in[0];
    const float* rel_enc  = (const float*)d_in[1];
    const float* rel_dec  = (const float*)d_in[2];
    const float* enc_ln1  = (const float*)d_in[3];
    const float* enc_wq   = (const float*)d_in[4];
    const float* enc_wk   = (const float*)d_in[5];
    const float* enc_wv   = (const float*)d_in[6];
    const float* enc_wo   = (const float*)d_in[7];
    const float* enc_ln2  = (const float*)d_in[8];
    const float* enc_wi   = (const float*)d_in[9];
    const float* enc_wmo  = (const float*)d_in[10];
    const float* enc_norm = (const float*)d_in[11];
    const float* dec_ln1  = (const float*)d_in[12];
    const float* dec_sq   = (const float*)d_in[13];
    const float* dec_sk   = (const float*)d_in[14];
    const float* dec_sv   = (const float*)d_in[15];
    const float* dec_so   = (const float*)d_in[16];
    const float* dec_ln2  = (const float*)d_in[17];
    const float* dec_cq   = (const float*)d_in[18];
    const float* dec_ck   = (const float*)d_in[19];
    const float* dec_cv   = (const float*)d_in[20];
    const float* dec_co   = (const float*)d_in[21];
    const float* dec_ln3  = (const float*)d_in[22];
    const float* dec_wi   = (const float*)d_in[23];
    const float* dec_wmo  = (const float*)d_in[24];
    const float* dec_norm = (const float*)d_in[25];
    const float* logits_w = (const float*)d_in[26];
    const int* enc_tok    = (const int*)d_in[27];
    const int* dec_in_tok = (const int*)d_in[28];
    const int* dec_tgt    = (const int*)d_in[29];

    float *xe, *xd;
    __half *enc, *h, *qkv, *q, *kv6, *ao, *hid, *be, *bd;
    __half *wAe, *woe, *wAs, *wos, *cqT, *ckvT, *coT, *wie, *wmoe, *wid_, *wmod, *logT;
    int *ve, *vt, *lutE, *lutD;
    cudaGetSymbolAddress((void**)&xe, g_xe);     cudaGetSymbolAddress((void**)&xd, g_xd);
    cudaGetSymbolAddress((void**)&enc, g_enc);   cudaGetSymbolAddress((void**)&h, g_h);
    cudaGetSymbolAddress((void**)&qkv, g_qkv);   cudaGetSymbolAddress((void**)&q, g_q);
    cudaGetSymbolAddress((void**)&kv6, g_kv6);   cudaGetSymbolAddress((void**)&ao, g_ao);
    cudaGetSymbolAddress((void**)&hid, g_hid);
    cudaGetSymbolAddress((void**)&be, g_bias_e); cudaGetSymbolAddress((void**)&bd, g_bias_d);
    cudaGetSymbolAddress((void**)&ve, g_val_e);  cudaGetSymbolAddress((void**)&vt, g_val_t);
    cudaGetSymbolAddress((void**)&lutE, g_lut_e); cudaGetSymbolAddress((void**)&lutD, g_lut_d);
    cudaGetSymbolAddress((void**)&wAe, g_wA_e);  cudaGetSymbolAddress((void**)&woe, g_wo_e);
    cudaGetSymbolAddress((void**)&wAs, g_wA_s);  cudaGetSymbolAddress((void**)&wos, g_wo_s);
    cudaGetSymbolAddress((void**)&cqT, g_cqT);   cudaGetSymbolAddress((void**)&ckvT, g_ckvT);
    cudaGetSymbolAddress((void**)&coT, g_coT);   cudaGetSymbolAddress((void**)&wie, g_wiT_e);
    cudaGetSymbolAddress((void**)&wmoe, g_wmoT_e); cudaGetSymbolAddress((void**)&wid_, g_wiT_d);
    cudaGetSymbolAddress((void**)&wmod, g_wmoT_d); cudaGetSymbolAddress((void**)&logT, g_logT);

    set_attrs();

    valid2_k<<<(2 * NT) / 256, 256>>>(enc_tok, dec_tgt, ve, vt);
    build_lut<<<4, 256>>>(lutE, lutD);
    build_bias_h<<<(TT * TT) / 256, 256>>>(rel_enc, lutE, be);
    build_bias_h<<<(TT * TT) / 256, 256>>>(rel_dec, lutD, bd);

    {
        P12 s;
        s.p[0] = enc_wq; s.p[1] = enc_wk; s.p[2] = enc_wv; s.p[3] = enc_wo;
        s.p[4] = dec_sq; s.p[5] = dec_sk; s.p[6] = dec_sv; s.p[7] = dec_so;
        s.p[8] = dec_cq; s.p[9] = dec_ck; s.p[10] = dec_cv; s.p[11] = dec_co;
        D8 d; d.wAe = wAe; d.woe = woe; d.wAs = wAs; d.wos = wos;
        d.cqT = cqT; d.ckvT = ckvT; d.coT = coT;
        transpose12<<<dim3(24, 24, 72), dim3(32, 8)>>>(s, d);
    }
    transpose_b<<<dim3(MM / 32, DD / 32, 6), dim3(32, 8)>>>(enc_wi,  wie,  DD, MM, DMM, DMM);
    transpose_b<<<dim3(DD / 32, MM / 32, 6), dim3(32, 8)>>>(enc_wmo, wmoe, MM, DD, DMM, DMM);
    transpose_b<<<dim3(MM / 32, DD / 32, 6), dim3(32, 8)>>>(dec_wi,  wid_, DD, MM, DMM, DMM);
    transpose_b<<<dim3(DD / 32, MM / 32, 6), dim3(32, 8)>>>(dec_wmo, wmod, MM, DD, DMM, DMM);
    transpose_b<<<dim3(VV / 32, DD / 32, 1), dim3(32, 8)>>>(logits_w, logT, DD, VV, 0, 0);

    const long QS = 3 * WSZ;

    auto self_attn = [&](const __half* hin, const __half* wqkvT, const __half* woT, float* x,
                         const __half* bias, const int* vQ, const int* vK, int causal) {
        gemm_h<false, false, true><<<dim3(18, 16), 128, SMEM_G>>>(hin, wqkvT, qkv, DD, DD, DD, 2304);
        flash_attn<<<dim3(4, 48), 256, FASMEM>>>(qkv, 2304, qkv + 768, 2304, qkv + 1536, 2304,
                                                 bias, vQ, vK, causal, ao);
        gemm_m64<true, false, false><<<dim3(6, 32), 256, SMEM_M64>>>(ao, woT, x, DD, DD, DD, DD);
    };
    auto mlp = [&](const __half* hin, const __half* wiT, const __half* wmoT, float* x) {
        gemm_h<false, true, true><<<dim3(24, 16), 128, SMEM_G>>>(hin, wiT, hid, DD, DD, DD, MM);
        gemm_m64<true, false, false><<<dim3(6, 32), 256, SMEM_M64>>>(hid, wmoT, x, MM, MM, MM, DD);
    };

    // -------- encoder --------
    embed_k<<<NT, 256>>>(enc_tok, emb, xe);
    for (int l = 0; l < LL; l++) {
        rmsnorm_k<<<NT, 192>>>(xe, enc_ln1 + (size_t)l * DD, h);
        self_attn(h, wAe + l * QS, woe + l * WSZ, xe, be, ve, ve, 0);
        rmsnorm_k<<<NT, 192>>>(xe, enc_ln2 + (size_t)l * DD, h);
        mlp(h, wie + l * DMM, wmoe + l * DMM, xe);
    }
    rmsnorm_k<<<NT, 192>>>(xe, enc_norm, enc);

    // -------- decoder --------
    embed_k<<<NT, 256>>>(dec_in_tok, emb, xd);
    gemm_h<false, false, true><<<dim3(KV6LD / 128, 16), 128, SMEM_G>>>(
        enc, ckvT, kv6, DD, DD, DD, KV6LD);

    for (int l = 0; l < LL; l++) {
        rmsnorm_k<<<NT, 192>>>(xd, dec_ln1 + (size_t)l * DD, h);
        self_attn(h, wAs + l * QS, wos + l * WSZ, xd, bd, vt, vt, 1);
        rmsnorm_k<<<NT, 192>>>(xd, dec_ln2 + (size_t)l * DD, h);
        gemm_m64<false, false, true><<<dim3(6, 32), 256, SMEM_M64>>>(h, cqT + l * WSZ, q, DD, DD, DD, DD);
        flash_attn<<<dim3(4, 48), 256, FASMEM>>>(q, DD,
                                                 kv6 + (long)l * 1536, KV6LD,
                                                 kv6 + (long)l * 1536 + 768, KV6LD,
                                                 nullptr, vt, ve, 0, ao);
        gemm_m64<true, false, false><<<dim3(6, 32), 256, SMEM_M64>>>(ao, coT + l * WSZ, xd, DD, DD, DD, DD);
        rmsnorm_k<<<NT, 192>>>(xd, dec_ln3 + (size_t)l * DD, h);
        mlp(h, wid_ + l * DMM, wmod + l * DMM, xd);
    }
    rmsnorm_k<<<NT, 192>>>(xd, dec_norm, h);

    // -------- logits --------
    gemm_h<false, false, false><<<dim3(251, 16), 128, SMEM_G>>>(h, logT, (float*)d_out, DD, DD, DD, VV);
}

// round 14
// speedup vs baseline: 1.0074x; 1.0074x over previous
#include <cuda_runtime.h>
#include <cuda_fp16.h>
#include <math.h>
#include <stdint.h>

#define TT 512
#define BBATCH 4
#define NT 2048
#define DD 768
#define HH 12
#define HDIM 64
#define MM 3072
#define VV 32128
#define LL 6
#define NEGINF -1e10f
#define WSZ ((long)DD * DD)
#define DMM ((long)DD * MM)
#define KV6LD (LL * 1536)   // 9216

// ---------------- scratch ----------------
__device__ float  g_xe[NT * DD];
__device__ float  g_xd[NT * DD];
__device__ __half g_enc[NT * DD];
__device__ __half g_h[NT * DD];
__device__ __half g_qkv[NT * 3 * DD];
__device__ __half g_q[NT * DD];
__device__ __half g_kv6[(long)NT * KV6LD];
__device__ __half g_ao[NT * DD];
__device__ __half g_hid[NT * MM];
__device__ __half g_bias_e[HH * TT * TT];
__device__ __half g_bias_d[HH * TT * TT];
__device__ int    g_lut_e[1023];
__device__ int    g_lut_d[1023];
__device__ int    g_val_e[NT];
__device__ int    g_val_t[NT];
// transposed fp16 weights [N,K]
__device__ __half g_wA_e[LL * 3 * DD * DD];
__device__ __half g_wo_e[LL * DD * DD];
__device__ __half g_wA_s[LL * 3 * DD * DD];
__device__ __half g_wo_s[LL * DD * DD];
__device__ __half g_cqT [LL * DD * DD];
__device__ __half g_ckvT[LL * 2 * DD * DD];
__device__ __half g_coT [LL * DD * DD];
__device__ __half g_wiT_e [LL * DD * MM];
__device__ __half g_wmoT_e[LL * DD * MM];
__device__ __half g_wiT_d [LL * DD * MM];
__device__ __half g_wmoT_d[LL * DD * MM];
__device__ __half g_logT[(long)VV * DD];

// ---------------- helpers ----------------
__device__ __forceinline__ void cp16(unsigned dst, const void* src)
{ asm volatile("cp.async.cg.shared.global [%0], [%1], 16;\n" :: "r"(dst), "l"(src)); }
__device__ __forceinline__ void cp_commit() { asm volatile("cp.async.commit_group;\n"); }
__device__ __forceinline__ void cp_wait1()  { asm volatile("cp.async.wait_group 1;\n"); }
__device__ __forceinline__ void cp_wait0()  { asm volatile("cp.async.wait_group 0;\n"); }

__device__ __forceinline__ unsigned su32(const void* p)
{ return (unsigned)__cvta_generic_to_shared(p); }

__device__ __forceinline__ void ldsm4(unsigned a_, unsigned* a)
{
    asm volatile("ldmatrix.sync.aligned.m8n8.x4.shared.b16 {%0,%1,%2,%3}, [%4];"
                 : "=r"(a[0]), "=r"(a[1]), "=r"(a[2]), "=r"(a[3]) : "r"(a_));
}
__device__ __forceinline__ void ldsm2(unsigned a_, unsigned* b)
{
    asm volatile("ldmatrix.sync.aligned.m8n8.x2.shared.b16 {%0,%1}, [%2];"
                 : "=r"(b[0]), "=r"(b[1]) : "r"(a_));
}
__device__ __forceinline__ void ldsm2t(unsigned a_, unsigned* b)
{
    asm volatile("ldmatrix.sync.aligned.m8n8.x2.trans.shared.b16 {%0,%1}, [%2];"
                 : "=r"(b[0]), "=r"(b[1]) : "r"(a_));
}
__device__ __forceinline__ void mma16(float* c, const unsigned* a, const unsigned* b)
{
    asm volatile("mma.sync.aligned.m16n8k16.row.col.f32.f16.f16.f32 "
                 "{%0,%1,%2,%3}, {%4,%5,%6,%7}, {%8,%9}, {%0,%1,%2,%3};"
                 : "+f"(c[0]), "+f"(c[1]), "+f"(c[2]), "+f"(c[3])
                 : "r"(a[0]), "r"(a[1]), "r"(a[2]), "r"(a[3]), "r"(b[0]), "r"(b[1]));
}

// ---------------- transposes ----------------
__global__ void transpose_b(const float* __restrict__ src, __half* __restrict__ dst,
                            int K, int N, long ss, long ds)
{
    __shared__ float t[32][33];
    const float* S = src + (long)blockIdx.z * ss;
    __half* D = dst + (long)blockIdx.z * ds;
    int k0 = blockIdx.y * 32, n0 = blockIdx.x * 32;
    int tx = threadIdx.x, ty = threadIdx.y;
#pragma unroll
    for (int i = 0; i < 32; i += 8)
        t[ty + i][tx] = S[(long)(k0 + ty + i) * N + n0 + tx];
    __syncthreads();
#pragma unroll
    for (int i = 0; i < 32; i += 8)
        D[(long)(n0 + ty + i) * K + k0 + tx] = __float2half_rn(t[tx][ty + i]);
}

struct P12 { const float* p[12]; };
struct D8  { __half* wAe; __half* woe; __half* wAs; __half* wos;
             __half* cqT; __half* ckvT; __half* coT; };

__global__ void transpose12(P12 srcs, D8 d)
{
    __shared__ float t[32][33];
    const int mat = blockIdx.z, layer = mat / 12, which = mat % 12;
    const float* S = srcs.p[which] + (long)layer * WSZ;
    __half* D;
    if (which < 3)       D = d.wAe + (long)layer * 3 * WSZ + (long)which * WSZ;
    else if (which == 3) D = d.woe + (long)layer * WSZ;
    else if (which < 7)  D = d.wAs + (long)layer * 3 * WSZ + (long)(which - 4) * WSZ;
    else if (which == 7) D = d.wos + (long)layer * WSZ;
    else if (which == 8) D = d.cqT + (long)layer * WSZ;
    else if (which < 11) D = d.ckvT + (long)layer * 2 * WSZ + (long)(which - 9) * WSZ;
    else                 D = d.coT + (long)layer * WSZ;
    int k0 = blockIdx.y * 32, n0 = blockIdx.x * 32;
    int tx = threadIdx.x, ty = threadIdx.y;
#pragma unroll
    for (int i = 0; i < 32; i += 8)
        t[ty + i][tx] = S[(long)(k0 + ty + i) * DD + n0 + tx];
    __syncthreads();
#pragma unroll
    for (int i = 0; i < 32; i += 8)
        D[(long)(n0 + ty + i) * DD + k0 + tx] = __float2half_rn(t[tx][ty + i]);
}

// ---------------- relpos bucket LUT + bias tables ----------------
__global__ void build_lut(int* __restrict__ lE, int* __restrict__ lD)
{
    int i = blockIdx.x * 256 + threadIdx.x;
    if (i >= 1023) return;
    int n = i - 511;
    {
        int ret = (n < 0) ? 16 : 0;
        int na = n < 0 ? -n : n;
        int bk;
        if (na < 8) bk = ret + na;
        else { int v = 8 + (int)(log((double)na / 8.0) / log(16.0) * 8.0); bk = ret + (v < 15 ? v : 15); }
        lE[i] = bk;
    }
    {
        int na = n > 0 ? n : 0;
        int bk;
        if (na < 16) bk = na;
        else { int v = 16 + (int)(log((double)na / 16.0) / log(8.0) * 16.0); bk = (v < 31 ? v : 31); }
        lD[i] = bk;
    }
}

// both bias tables in one launch: blockIdx.y selects enc/dec
__global__ void build_bias2(const float* __restrict__ relE, const int* __restrict__ lutE,
                            __half* __restrict__ biasE,
                            const float* __restrict__ relD, const int* __restrict__ lutD,
                            __half* __restrict__ biasD)
{
    const float* rel = blockIdx.y ? relD : relE;
    const int* lut   = blockIdx.y ? lutD : lutE;
    __half* bias     = blockIdx.y ? biasD : biasE;
    int idx = blockIdx.x * 256 + threadIdx.x;
    int q = idx / TT, s = idx % TT;
    int bk = lut[q - s + 511];
#pragma unroll
    for (int h = 0; h < HH; h++)
        bias[(long)h * TT * TT + idx] = __float2half_rn(rel[h * 32 + bk]);
}

// ---------------- tile loaders ----------------
__device__ __forceinline__ void load_tileH128(unsigned sbase, const __half* P,
                                              int row0, int k0, int ld, int tid)
{
#pragma unroll
    for (int j = 0; j < 8; j++) {
        int c = tid + 128 * j, m = c >> 3, kc = c & 7;
        cp16(sbase + ((m * 8 + (kc ^ (m & 7))) << 4),
             P + (long)(row0 + m) * ld + k0 + kc * 8);
    }
}
__device__ __forceinline__ void load_tileH256(unsigned sbase, const __half* P,
                                              int row0, int k0, int ld, int tid)
{
#pragma unroll
    for (int j = 0; j < 4; j++) {
        int c = tid + 256 * j, m = c >> 3, kc = c & 7;
        cp16(sbase + ((m * 8 + (kc ^ (m & 7))) << 4),
             P + (long)(row0 + m) * ld + k0 + kc * 8);
    }
}

// ---------------- fp16 NT GEMM, 4 warps / 64x64 warp tiles (big grids) ----------------
template<bool ACC, bool RELU, bool OUTH>
__global__ __launch_bounds__(128) void gemm_h(
    const __half* __restrict__ A, const __half* __restrict__ Bt, void* __restrict__ Cv,
    int K, int lda, int ldb, int ldc)
{
    extern __shared__ char smc[];
    const unsigned asb = su32(smc);
    const unsigned bsb = asb + 32768;
    constexpr int STG = 16384;

    const int tid = threadIdx.x, lane = tid & 31, warp = tid >> 5;
    const int mw = (warp & 1) * 64, nw = (warp >> 1) * 64;
    const int m0 = blockIdx.y * 128, n0 = blockIdx.x * 128;

    float acc[4][8][4];
#pragma unroll
    for (int i = 0; i < 4; i++)
#pragma unroll
        for (int j = 0; j < 8; j++)
#pragma unroll
            for (int q = 0; q < 4; q++) acc[i][j][q] = 0.f;

    const int nk = K >> 6;
    load_tileH128(asb, A, m0, 0, lda, tid);
    load_tileH128(bsb, Bt, n0, 0, ldb, tid);
    cp_commit();

    for (int kt = 0; kt < nk; kt++) {
        const int st = kt & 1;
        if (kt + 1 < nk) {
            load_tileH128(asb + (st ^ 1) * STG, A, m0, (kt + 1) << 6, lda, tid);
            load_tileH128(bsb + (st ^ 1) * STG, Bt, n0, (kt + 1) << 6, ldb, tid);
        }
        cp_commit();
        cp_wait1();
        __syncthreads();

        const unsigned ab = asb + st * STG;
        const unsigned bb = bsb + st * STG;
#pragma unroll
        for (int kk = 0; kk < 64; kk += 16) {
            unsigned a[4][4];
#pragma unroll
            for (int i = 0; i < 4; i++) {
                int r = mw + 16 * i + (lane & 15);
                int ch = (kk >> 3) + (lane >> 4);
                ldsm4(ab + ((r * 8 + (ch ^ (r & 7))) << 4), a[i]);
            }
            unsigned bf[8][2];
#pragma unroll
            for (int jj = 0; jj < 4; jj++) {
                unsigned t4[4];
                int r = nw + 16 * jj + ((lane >> 4) << 3) + (lane & 7);
                int ch = (kk >> 3) + ((lane >> 3) & 1);
                ldsm4(bb + ((r * 8 + (ch ^ (r & 7))) << 4), t4);
                bf[2 * jj][0] = t4[0]; bf[2 * jj][1] = t4[1];
                bf[2 * jj + 1][0] = t4[2]; bf[2 * jj + 1][1] = t4[3];
            }
#pragma unroll
            for (int i = 0; i < 4; i++)
#pragma unroll
                for (int j = 0; j < 8; j++) mma16(acc[i][j], a[i], bf[j]);
        }
        __syncthreads();
    }

#pragma unroll
    for (int i = 0; i < 4; i++) {
        int r = m0 + mw + 16 * i + (lane >> 2);
#pragma unroll
        for (int j = 0; j < 8; j++) {
            int cn = n0 + nw + 8 * j + ((lane & 3) << 1);
            float2 v0 = make_float2(acc[i][j][0], acc[i][j][1]);
            float2 v1 = make_float2(acc[i][j][2], acc[i][j][3]);
            if (RELU) {
                v0.x = fmaxf(v0.x, 0.f); v0.y = fmaxf(v0.y, 0.f);
                v1.x = fmaxf(v1.x, 0.f); v1.y = fmaxf(v1.y, 0.f);
            }
            if (OUTH) {
                __half* C = (__half*)Cv;
                *(__half2*)(C + (long)r * ldc + cn)       = __floats2half2_rn(v0.x, v0.y);
                *(__half2*)(C + (long)(r + 8) * ldc + cn) = __floats2half2_rn(v1.x, v1.y);
            } else {
                float* C = (float*)Cv;
                float2* p0 = (float2*)(C + (long)r * ldc + cn);
                float2* p1 = (float2*)(C + (long)(r + 8) * ldc + cn);
                if (ACC) {
                    float2 o0 = *p0, o1 = *p1;
                    v0.x += o0.x; v0.y += o0.y; v1.x += o1.x; v1.y += o1.y;
                }
                *p0 = v0; *p1 = v1;
            }
        }
    }
}

// ---------------- fp16 NT GEMM, 8 warps / 64x32 warp tiles (small grids) ----------------
template<bool ACC, bool RELU, bool OUTH>
__global__ __launch_bounds__(256) void gemm_h8(
    const __half* __restrict__ A, const __half* __restrict__ Bt, void* __restrict__ Cv,
    int K, int lda, int ldb, int ldc)
{
    extern __shared__ char smc[];
    const unsigned asb = su32(smc);
    const unsigned bsb = asb + 32768;
    constexpr int STG = 16384;

    const int tid = threadIdx.x, lane = tid & 31, warp = tid >> 5;
    const int mw = (warp & 1) * 64, nw = (warp >> 1) * 32;
    const int m0 = blockIdx.y * 128, n0 = blockIdx.x * 128;

    float acc[4][4][4];
#pragma unroll
    for (int i = 0; i < 4; i++)
#pragma unroll
        for (int j = 0; j < 4; j++)
#pragma unroll
            for (int q = 0; q < 4; q++) acc[i][j][q] = 0.f;

    const int nk = K >> 6;
    load_tileH256(asb, A, m0, 0, lda, tid);
    load_tileH256(bsb, Bt, n0, 0, ldb, tid);
    cp_commit();

    for (int kt = 0; kt < nk; kt++) {
        const int st = kt & 1;
        if (kt + 1 < nk) {
            load_tileH256(asb + (st ^ 1) * STG, A, m0, (kt + 1) << 6, lda, tid);
            load_tileH256(bsb + (st ^ 1) * STG, Bt, n0, (kt + 1) << 6, ldb, tid);
        }
        cp_commit();
        cp_wait1();
        __syncthreads();

        const unsigned ab = asb + st * STG;
        const unsigned bb = bsb + st * STG;
#pragma unroll
        for (int kk = 0; kk < 64; kk += 16) {
            unsigned a[4][4];
#pragma unroll
            for (int i = 0; i < 4; i++) {
                int r = mw + 16 * i + (lane & 15);
                int ch = (kk >> 3) + (lane >> 4);
                ldsm4(ab + ((r * 8 + (ch ^ (r & 7))) << 4), a[i]);
            }
            unsigned bf[4][2];
#pragma unroll
            for (int j = 0; j < 4; j++) {
                int r = nw + 8 * j + (lane & 7);
                int ch = (kk >> 3) + ((lane >> 3) & 1);
                ldsm2(bb + ((r * 8 + (ch ^ (r & 7))) << 4), bf[j]);
            }
#pragma unroll
            for (int i = 0; i < 4; i++)
#pragma unroll
                for (int j = 0; j < 4; j++) mma16(acc[i][j], a[i], bf[j]);
        }
        __syncthreads();
    }

#pragma unroll
    for (int i = 0; i < 4; i++) {
        int r = m0 + mw + 16 * i + (lane >> 2);
#pragma unroll
        for (int j = 0; j < 4; j++) {
            int cn = n0 + nw + 8 * j + ((lane & 3) << 1);
            float2 v0 = make_float2(acc[i][j][0], acc[i][j][1]);
            float2 v1 = make_float2(acc[i][j][2], acc[i][j][3]);
            if (RELU) {
                v0.x = fmaxf(v0.x, 0.f); v0.y = fmaxf(v0.y, 0.f);
                v1.x = fmaxf(v1.x, 0.f); v1.y = fmaxf(v1.y, 0.f);
            }
            if (OUTH) {
                __half* C = (__half*)Cv;
                *(__half2*)(C + (long)r * ldc + cn)       = __floats2half2_rn(v0.x, v0.y);
                *(__half2*)(C + (long)(r + 8) * ldc + cn) = __floats2half2_rn(v1.x, v1.y);
            } else {
                float* C = (float*)Cv;
                float2* p0 = (float2*)(C + (long)r * ldc + cn);
                float2* p1 = (float2*)(C + (long)(r + 8) * ldc + cn);
                if (ACC) {
                    float2 o0 = *p0, o1 = *p1;
                    v0.x += o0.x; v0.y += o0.y; v1.x += o1.x; v1.y += o1.y;
                }
                *p0 = v0; *p1 = v1;
            }
        }
    }
}

// ================= fused flash attention (fp16 operands, half bias) =================
#define BQ   0
#define BKT  16384
#define BV   49152
#define BP   65536
#define BRED 98304
#define BVK  100352
#define BVQ  102400
#define FASMEM 104448

__global__ __launch_bounds__(256) void flash_attn(
    const __half* __restrict__ Q, int ldq,
    const __half* __restrict__ K, int ldk,
    const __half* __restrict__ V, int ldv,
    const __half* __restrict__ bias,
    const int* __restrict__ validQ, const int* __restrict__ validK,
    int causal, __half* __restrict__ O)
{
    extern __shared__ char smc[];
    float* smf = (float*)smc;
    int* smi = (int*)smc;
    __shared__ int s_anyinvalid;
    const unsigned sb = su32(smc);
    const int tid = threadIdx.x, lane = tid & 31, warp = tid >> 5;
    const int mw = (warp & 3) * 32;
    const int nwid = warp >> 2;
    const int nw = nwid * 64;
    const int nhd = nwid * 32;
    const int q0 = blockIdx.x * 128;
    const int z = blockIdx.y, b = z / HH, h = z % HH;
    const __half* Qp = Q + (long)b * TT * ldq + h * HDIM;
    const __half* Kp = K + (long)b * TT * ldk + h * HDIM;
    const __half* Vp = V + (long)b * TT * ldv + h * HDIM;
    const __half* biasH = bias ? bias + (long)h * TT * TT : nullptr;
    const int nt = TT / 128;

    auto loadQ = [&]() {
#pragma unroll
        for (int j = 0; j < 4; j++) {
            int c = tid + 256 * j, m = c >> 3, kc = c & 7;
            cp16(sb + BQ + ((m * 8 + (kc ^ (m & 7))) << 4),
                 Qp + (long)(q0 + m) * ldq + kc * 8);
        }
    };
    auto loadK = [&](int buf, int st) {
        int s0 = st * 128;
#pragma unroll
        for (int j = 0; j < 4; j++) {
            int c = tid + 256 * j, m = c >> 3, kc = c & 7;
            cp16(sb + BKT + buf * 16384 + ((m * 8 + (kc ^ (m & 7))) << 4),
                 Kp + (long)(s0 + m) * ldk + kc * 8);
        }
    };
    auto loadV = [&](int st) {
        int s0 = st * 128;
#pragma unroll
        for (int j = 0; j < 4; j++) {
            int c = tid + 256 * j, k = c >> 3, nc = c & 7;
            cp16(sb + BV + ((k * 8 + (nc ^ (k & 7))) << 4),
                 Vp + (long)(s0 + k) * ldv + nc * 8);
        }
    };

    loadQ(); loadK(0, 0); cp_commit();
    loadV(0); cp_commit();
    loadK(1, 1); cp_commit();

    smi[(BVK >> 2) + tid] = validK[b * TT + tid];
    smi[(BVK >> 2) + 256 + tid] = validK[b * TT + 256 + tid];
    smi[(BVQ >> 2) + tid] = validQ[b * TT + tid];
    smi[(BVQ >> 2) + 256 + tid] = validQ[b * TT + 256 + tid];
    if (tid == 0) s_anyinvalid = 0;

    cp_wait1();
    __syncthreads();

    int nt_eff = nt;
    if (causal) {
        if (tid < 128 && smi[(BVQ >> 2) + q0 + tid] == 0) s_anyinvalid = 1;
        __syncthreads();
        if (!s_anyinvalid) nt_eff = blockIdx.x + 1;
        __syncthreads();
    }

    float m_run[2][2], s_run[2][2], oacc[2][4][4];
#pragma unroll
    for (int i = 0; i < 2; i++)
#pragma unroll
        for (int rr = 0; rr < 2; rr++) { m_run[i][rr] = -3.0e38f; s_run[i][rr] = 0.f; }
#pragma unroll
    for (int i = 0; i < 2; i++)
#pragma unroll
        for (int j = 0; j < 4; j++)
#pragma unroll
            for (int q = 0; q < 4; q++) oacc[i][j][q] = 0.f;

    for (int t = 0; t < nt_eff; t++) {
        if (t >= 1) {
            loadV(t); cp_commit();
            if (t + 1 < nt_eff) { loadK((t + 1) & 1, t + 1); cp_commit(); }
        }
        const int s0 = t * 128;

        float acc[2][8][4];
#pragma unroll
        for (int i = 0; i < 2; i++)
#pragma unroll
            for (int j = 0; j < 8; j++)
#pragma unroll
                for (int q = 0; q < 4; q++) acc[i][j][q] = 0.f;

        const unsigned kb = sb + BKT + (t & 1) * 16384;
#pragma unroll
        for (int kk = 0; kk < 64; kk += 16) {
            unsigned a[2][4];
#pragma unroll
            for (int i = 0; i < 2; i++) {
                int r = mw + 16 * i + (lane & 15);
                int ch = (kk >> 3) + (lane >> 4);
                ldsm4(sb + BQ + ((r * 8 + (ch ^ (r & 7))) << 4), a[i]);
            }
            unsigned bf[8][2];
#pragma unroll
            for (int j = 0; j < 8; j++) {
                int r = nw + 8 * j + (lane & 7);
                int ch = (kk >> 3) + ((lane >> 3) & 1);
                ldsm2(kb + ((r * 8 + (ch ^ (r & 7))) << 4), bf[j]);
            }
#pragma unroll
            for (int i = 0; i < 2; i++)
#pragma unroll
                for (int j = 0; j < 8; j++) mma16(acc[i][j], a[i], bf[j]);
        }

        // bias + mask
#pragma unroll
        for (int i = 0; i < 2; i++)
#pragma unroll
            for (int rr = 0; rr < 2; rr++) {
                int Rl = mw + 16 * i + 8 * rr + (lane >> 2);
                int q = q0 + Rl;
                int vq = smi[(BVQ >> 2) + q];
#pragma unroll
                for (int j = 0; j < 8; j++) {
                    int Cl = nw + 8 * j + 2 * (lane & 3);
                    int s = s0 + Cl;
                    float b0 = 0.f, b1 = 0.f;
                    if (biasH) {
                        __half2 bb = *(const __half2*)(biasH + (long)q * TT + s);
                        b0 = __half2float(__low2half(bb));
                        b1 = __half2float(__high2half(bb));
                    }
                    int2 vk = *(const int2*)(smi + (BVK >> 2) + s);
                    float v0 = acc[i][j][2 * rr + 0] + b0;
                    float v1 = acc[i][j][2 * rr + 1] + b1;
                    bool m0 = vq && vk.x && (!causal || s <= q);
                    bool m1 = vq && vk.y && (!causal || s + 1 <= q);
                    acc[i][j][2 * rr + 0] = m0 ? v0 : NEGINF;
                    acc[i][j][2 * rr + 1] = m1 ? v1 : NEGINF;
                }
            }

        // row max
        float mp[2][2];
#pragma unroll
        for (int i = 0; i < 2; i++)
#pragma unroll
            for (int rr = 0; rr < 2; rr++) {
                float m = -3.4e38f;
#pragma unroll
                for (int j = 0; j < 8; j++)
                    m = fmaxf(m, fmaxf(acc[i][j][2 * rr], acc[i][j][2 * rr + 1]));
                mp[i][rr] = m;
            }
#pragma unroll
        for (int o = 1; o <= 2; o <<= 1)
#pragma unroll
            for (int i = 0; i < 2; i++)
#pragma unroll
                for (int rr = 0; rr < 2; rr++)
                    mp[i][rr] = fmaxf(mp[i][rr], __shfl_xor_sync(0xffffffffu, mp[i][rr], o));
        if ((lane & 3) == 0) {
#pragma unroll
            for (int i = 0; i < 2; i++)
#pragma unroll
                for (int rr = 0; rr < 2; rr++) {
                    int Rl = mw + 16 * i + 8 * rr + (lane >> 2);
                    smf[(BRED >> 2) + Rl * 2 + nwid] = mp[i][rr];
                }
        }
        __syncthreads();

        float mnew[2][2], scl[2][2];
#pragma unroll
        for (int i = 0; i < 2; i++)
#pragma unroll
            for (int rr = 0; rr < 2; rr++) {
                int Rl = mw + 16 * i + 8 * rr + (lane >> 2);
                float mt = fmaxf(smf[(BRED >> 2) + Rl * 2], smf[(BRED >> 2) + Rl * 2 + 1]);
                float mn = fmaxf(m_run[i][rr], mt);
                scl[i][rr] = __expf(m_run[i][rr] - mn);
                m_run[i][rr] = mn;
                mnew[i][rr] = mn;
            }

        // p = exp(s-m), stage P (fp16), partial sums
        float sp[2][2] = {{0.f, 0.f}, {0.f, 0.f}};
#pragma unroll
        for (int i = 0; i < 2; i++)
#pragma unroll
            for (int rr = 0; rr < 2; rr++) {
                int Rl = mw + 16 * i + 8 * rr + (lane >> 2);
#pragma unroll
                for (int j = 0; j < 8; j++) {
                    float p0 = __expf(acc[i][j][2 * rr + 0] - mnew[i][rr]);
                    float p1 = __expf(acc[i][j][2 * rr + 1] - mnew[i][rr]);
                    sp[i][rr] += p0 + p1;
                    int Cl = nw + 8 * j + 2 * (lane & 3);
                    int nc = Cl >> 3;
                    *(__half2*)(smc + BP + Rl * 256 + ((nc ^ (Rl & 7)) << 4) + (Cl & 7) * 2) =
                        __floats2half2_rn(p0, p1);
                }
            }
#pragma unroll
        for (int o = 1; o <= 2; o <<= 1)
#pragma unroll
            for (int i = 0; i < 2; i++)
#pragma unroll
                for (int rr = 0; rr < 2; rr++)
                    sp[i][rr] += __shfl_xor_sync(0xffffffffu, sp[i][rr], o);
        if ((lane & 3) == 0) {
#pragma unroll
            for (int i = 0; i < 2; i++)
#pragma unroll
                for (int rr = 0; rr < 2; rr++) {
                    int Rl = mw + 16 * i + 8 * rr + (lane >> 2);
                    smf[(BRED >> 2) + 256 + Rl * 2 + nwid] = sp[i][rr];
                }
        }
        if (t + 1 < nt_eff) cp_wait1(); else cp_wait0();
        __syncthreads();

#pragma unroll
        for (int i = 0; i < 2; i++)
#pragma unroll
            for (int rr = 0; rr < 2; rr++) {
                int Rl = mw + 16 * i + 8 * rr + (lane >> 2);
                float st = smf[(BRED >> 2) + 256 + Rl * 2] + smf[(BRED >> 2) + 256 + Rl * 2 + 1];
                s_run[i][rr] = s_run[i][rr] * scl[i][rr] + st;
            }
#pragma unroll
        for (int i = 0; i < 2; i++)
#pragma unroll
            for (int j = 0; j < 4; j++) {
                oacc[i][j][0] *= scl[i][0]; oacc[i][j][1] *= scl[i][0];
                oacc[i][j][2] *= scl[i][1]; oacc[i][j][3] *= scl[i][1];
            }

        // PV
#pragma unroll
        for (int kk = 0; kk < 128; kk += 16) {
            unsigned a[2][4];
#pragma unroll
            for (int i = 0; i < 2; i++) {
                int r = mw + 16 * i + (lane & 15);
                int ch = (kk >> 3) + (lane >> 4);
                ldsm4(sb + BP + ((r * 16 + (ch ^ (r & 7))) << 4), a[i]);
            }
            unsigned bf[4][2];
#pragma unroll
            for (int j = 0; j < 4; j++) {
                int n0c = (nhd + 8 * j) >> 3;
                int r = kk + (lane & 7) + ((lane >> 3) & 1) * 8;
                ldsm2t(sb + BV + ((r * 8 + (n0c ^ (r & 7))) << 4), bf[j]);
            }
#pragma unroll
            for (int i = 0; i < 2; i++)
#pragma unroll
                for (int j = 0; j < 4; j++) mma16(oacc[i][j], a[i], bf[j]);
        }

        if (t + 1 < nt_eff) { cp_wait0(); __syncthreads(); }
    }

    __half* Op = O + (long)b * TT * DD + h * HDIM;
#pragma unroll
    for (int i = 0; i < 2; i++)
#pragma unroll
        for (int rr = 0; rr < 2; rr++) {
            int Rl = mw + 16 * i + 8 * rr + (lane >> 2);
            float inv = 1.0f / s_run[i][rr];
#pragma unroll
            for (int j = 0; j < 4; j++) {
                int cn = nhd + 8 * j + 2 * (lane & 3);
                *(__half2*)(Op + (long)(q0 + Rl) * DD + cn) =
                    __floats2half2_rn(oacc[i][j][2 * rr + 0] * inv,
                                      oacc[i][j][2 * rr + 1] * inv);
            }
        }
}

// ---------------- elementwise ----------------
__global__ __launch_bounds__(192) void rmsnorm_k(const float* __restrict__ X,
                                                 const float* __restrict__ scale,
                                                 __half* __restrict__ O)
{
    const int row = blockIdx.x, tid = threadIdx.x;
    float4 v = ((const float4*)(X + (long)row * DD))[tid];
    float s = v.x * v.x + v.y * v.y + v.z * v.z + v.w * v.w;
#pragma unroll
    for (int o = 16; o > 0; o >>= 1) s += __shfl_xor_sync(0xffffffffu, s, o);
    __shared__ float red[6];
    if ((tid & 31) == 0) red[tid >> 5] = s;
    __syncthreads();
    float tot = red[0] + red[1] + red[2] + red[3] + red[4] + red[5];
    float r = 1.0f / sqrtf(tot / (float)DD + 1e-6f);
    float4 sc = ((const float4*)scale)[tid];
    __half2* op = (__half2*)(O + (long)row * DD);
    op[2 * tid]     = __floats2half2_rn(v.x * r * sc.x, v.y * r * sc.y);
    op[2 * tid + 1] = __floats2half2_rn(v.z * r * sc.z, v.w * r * sc.w);
}

// both embeds in one launch at the start
__global__ void embed2_k(const int* __restrict__ tokE, const int* __restrict__ tokD,
                         const float* __restrict__ emb,
                         float* __restrict__ Oe, float* __restrict__ Od)
{
    int t = blockIdx.x;
    const int* tok = (t < NT) ? tokE : tokD;
    float* O = (t < NT) ? Oe : Od;
    int tt = (t < NT) ? t : t - NT;
    const float* e = emb + (size_t)tok[tt] * DD;
    for (int d = threadIdx.x; d < DD; d += 256) O[(size_t)tt * DD + d] = e[d];
}

__global__ void valid2_k(const int* __restrict__ tokA, const int* __restrict__ tokB,
                         int* __restrict__ vA, int* __restrict__ vB)
{
    int i = blockIdx.x * blockDim.x + threadIdx.x;
    if (i < NT) vA[i] = tokA[i] > 0 ? 1 : 0;
    else { int j = i - NT; vB[j] = tokB[j] > 0 ? 1 : 0; }
}

// ---------------- host ----------------
#define SMEM_G 65536

static void set_attrs()
{
    cudaFuncSetAttribute(gemm_h<false, false, true >, cudaFuncAttributeMaxDynamicSharedMemorySize, SMEM_G);
    cudaFuncSetAttribute(gemm_h<false, true,  true >, cudaFuncAttributeMaxDynamicSharedMemorySize, SMEM_G);
    cudaFuncSetAttribute(gemm_h<false, false, false>, cudaFuncAttributeMaxDynamicSharedMemorySize, SMEM_G);
    cudaFuncSetAttribute(gemm_h8<true,  false, false>, cudaFuncAttributeMaxDynamicSharedMemorySize, SMEM_G);
    cudaFuncSetAttribute(gemm_h8<false, false, true >, cudaFuncAttributeMaxDynamicSharedMemorySize, SMEM_G);
    cudaFuncSetAttribute(flash_attn, cudaFuncAttributeMaxDynamicSharedMemorySize, FASMEM);
}

extern "C" void kernel_launch(void* const* d_in, const int* in_sizes, int n_in,
                              void* d_out, int out_size)
{
    const float* emb      = (const float*)d_in[0];
    const float* rel_enc  = (const float*)d_in[1];
    const float* rel_dec  = (const float*)d_in[2];
    const float* enc_ln1  = (const float*)d_in[3];
    const float* enc_wq   = (const float*)d_in[4];
    const float* enc_wk   = (const float*)d_in[5];
    const float* enc_wv   = (const float*)d_in[6];
    const float* enc_wo   = (const float*)d_in[7];
    const float* enc_ln2  = (const float*)d_in[8];
    const float* enc_wi   = (const float*)d_in[9];
    const float* enc_wmo  = (const float*)d_in[10];
    const float* enc_norm = (const float*)d_in[11];
    const float* dec_ln1  = (const float*)d_in[12];
    const float* dec_sq   = (const float*)d_in[13];
    const float* dec_sk   = (const float*)d_in[14];
    const float* dec_sv   = (const float*)d_in[15];
    const float* dec_so   = (const float*)d_in[16];
    const float* dec_ln2  = (const float*)d_in[17];
    const float* dec_cq   = (const float*)d_in[18];
    const float* dec_ck   = (const float*)d_in[19];
    const float* dec_cv   = (const float*)d_in[20];
    const float* dec_co   = (const float*)d_in[21];
    const float* dec_ln3  = (const float*)d_in[22];
    const float* dec_wi   = (const float*)d_in[23];
    const float* dec_wmo  = (const float*)d_in[24];
    const float* dec_norm = (const float*)d_in[25];
    const float* logits_w = (const float*)d_in[26];
    const int* enc_tok    = (const int*)d_in[27];
    const int* dec_in_tok = (const int*)d_in[28];
    const int* dec_tgt    = (const int*)d_in[29];

    float *xe, *xd;
    __half *enc, *h, *qkv, *q, *kv6, *ao, *hid, *be, *bd;
    __half *wAe, *woe, *wAs, *wos, *cqT, *ckvT, *coT, *wie, *wmoe, *wid_, *wmod, *logT;
    int *ve, *vt, *lutE, *lutD;
    cudaGetSymbolAddress((void**)&xe, g_xe);     cudaGetSymbolAddress((void**)&xd, g_xd);
    cudaGetSymbolAddress((void**)&enc, g_enc);   cudaGetSymbolAddress((void**)&h, g_h);
    cudaGetSymbolAddress((void**)&qkv, g_qkv);   cudaGetSymbolAddress((void**)&q, g_q);
    cudaGetSymbolAddress((void**)&kv6, g_kv6);   cudaGetSymbolAddress((void**)&ao, g_ao);
    cudaGetSymbolAddress((void**)&hid, g_hid);
    cudaGetSymbolAddress((void**)&be, g_bias_e); cudaGetSymbolAddress((void**)&bd, g_bias_d);
    cudaGetSymbolAddress((void**)&ve, g_val_e);  cudaGetSymbolAddress((void**)&vt, g_val_t);
    cudaGetSymbolAddress((void**)&lutE, g_lut_e); cudaGetSymbolAddress((void**)&lutD, g_lut_d);
    cudaGetSymbolAddress((void**)&wAe, g_wA_e);  cudaGetSymbolAddress((void**)&woe, g_wo_e);
    cudaGetSymbolAddress((void**)&wAs, g_wA_s);  cudaGetSymbolAddress((void**)&wos, g_wo_s);
    cudaGetSymbolAddress((void**)&cqT, g_cqT);   cudaGetSymbolAddress((void**)&ckvT, g_ckvT);
    cudaGetSymbolAddress((void**)&coT, g_coT);   cudaGetSymbolAddress((void**)&wie, g_wiT_e);
    cudaGetSymbolAddress((void**)&wmoe, g_wmoT_e); cudaGetSymbolAddress((void**)&wid_, g_wiT_d);
    cudaGetSymbolAddress((void**)&wmod, g_wmoT_d); cudaGetSymbolAddress((void**)&logT, g_logT);

    set_attrs();

    valid2_k<<<(2 * NT) / 256, 256>>>(enc_tok, dec_tgt, ve, vt);
    build_lut<<<4, 256>>>(lutE, lutD);
    build_bias2<<<dim3((TT * TT) / 256, 2), 256>>>(rel_enc, lutE, be, rel_dec, lutD, bd);
    embed2_k<<<2 * NT, 256>>>(enc_tok, dec_in_tok, emb, xe, xd);

    {
        P12 s;
        s.p[0] = enc_wq; s.p[1] = enc_wk; s.p[2] = enc_wv; s.p[3] = enc_wo;
        s.p[4] = dec_sq; s.p[5] = dec_sk; s.p[6] = dec_sv; s.p[7] = dec_so;
        s.p[8] = dec_cq; s.p[9] = dec_ck; s.p[10] = dec_cv; s.p[11] = dec_co;
        D8 d; d.wAe = wAe; d.woe = woe; d.wAs = wAs; d.wos = wos;
        d.cqT = cqT; d.ckvT = ckvT; d.coT = coT;
        transpose12<<<dim3(24, 24, 72), dim3(32, 8)>>>(s, d);
    }
    transpose_b<<<dim3(MM / 32, DD / 32, 6), dim3(32, 8)>>>(enc_wi,  wie,  DD, MM, DMM, DMM);
    transpose_b<<<dim3(DD / 32, MM / 32, 6), dim3(32, 8)>>>(enc_wmo, wmoe, MM, DD, DMM, DMM);
    transpose_b<<<dim3(MM / 32, DD / 32, 6), dim3(32, 8)>>>(dec_wi,  wid_, DD, MM, DMM, DMM);
    transpose_b<<<dim3(DD / 32, MM / 32, 6), dim3(32, 8)>>>(dec_wmo, wmod, MM, DD, DMM, DMM);
    transpose_b<<<dim3(VV / 32, DD / 32, 1), dim3(32, 8)>>>(logits_w, logT, DD, VV, 0, 0);

    const long QS = 3 * WSZ;

    auto self_attn = [&](const __half* hin, const __half* wqkvT, const __half* woT, float* x,
                         const __half* bias, const int* vQ, const int* vK, int causal) {
        gemm_h<false, false, true><<<dim3(18, 16), 128, SMEM_G>>>(hin, wqkvT, qkv, DD, DD, DD, 2304);
        flash_attn<<<dim3(4, 48), 256, FASMEM>>>(qkv, 2304, qkv + 768, 2304, qkv + 1536, 2304,
                                                 bias, vQ, vK, causal, ao);
        gemm_h8<true, false, false><<<dim3(6, 16), 256, SMEM_G>>>(ao, woT, x, DD, DD, DD, DD);
    };
    auto mlp = [&](const __half* hin, const __half* wiT, const __half* wmoT, float* x) {
        gemm_h<false, true, true><<<dim3(24, 16), 128, SMEM_G>>>(hin, wiT, hid, DD, DD, DD, MM);
        gemm_h8<true, false, false><<<dim3(6, 16), 256, SMEM_G>>>(hid, wmoT, x, MM, MM, MM, DD);
    };

    // -------- encoder --------
    for (int l = 0; l < LL; l++) {
        rmsnorm_k<<<NT, 192>>>(xe, enc_ln1 + (size_t)l * DD, h);
        self_attn(h, wAe + l * QS, woe + l * WSZ, xe, be, ve, ve, 0);
        rmsnorm_k<<<NT, 192>>>(xe, enc_ln2 + (size_t)l * DD, h);
        mlp(h, wie + l * DMM, wmoe + l * DMM, xe);
    }
    rmsnorm_k<<<NT, 192>>>(xe, enc_norm, enc);

    // -------- decoder --------
    gemm_h<false, false, true><<<dim3(KV6LD / 128, 16), 128, SMEM_G>>>(
        enc, ckvT, kv6, DD, DD, DD, KV6LD);

    for (int l = 0; l < LL; l++) {
        rmsnorm_k<<<NT, 192>>>(xd, dec_ln1 + (size_t)l * DD, h);
        self_attn(h, wAs + l * QS, wos + l * WSZ, xd, bd, vt, vt, 1);
        rmsnorm_k<<<NT, 192>>>(xd, dec_ln2 + (size_t)l * DD, h);
        gemm_h8<false, false, true><<<dim3(6, 16), 256, SMEM_G>>>(h, cqT + l * WSZ, q, DD, DD, DD, DD);
        flash_attn<<<dim3(4, 48), 256, FASMEM>>>(q, DD,
                                                 kv6 + (long)l * 1536, KV6LD,
                                                 kv6 + (long)l * 1536 + 768, KV6LD,
                                                 nullptr, vt, ve, 0, ao);
        gemm_h8<true, false, false><<<dim3(6, 16), 256, SMEM_G>>>(ao, coT + l * WSZ, xd, DD, DD, DD, DD);
        rmsnorm_k<<<NT, 192>>>(xd, dec_ln3 + (size_t)l * DD, h);
        mlp(h, wid_ + l * DMM, wmod + l * DMM, xd);
    }
    rmsnorm_k<<<NT, 192>>>(xd, dec_norm, h);

    // -------- logits --------
    gemm_h<false, false, false><<<dim3(251, 16), 128, SMEM_G>>>(h, logT, (float*)d_out, DD, DD, DD, VV);
}

// round 16
// speedup vs baseline: 1.0189x; 1.0114x over previous
#include <cuda_runtime.h>
#include <cuda_fp16.h>
#include <math.h>
#include <stdint.h>

#define TT 512
#define BBATCH 4
#define NT 2048
#define DD 768
#define HH 12
#define HDIM 64
#define MM 3072
#define VV 32128
#define LL 6
#define NEGINF -1e10f
#define WSZ ((long)DD * DD)
#define DMM ((long)DD * MM)
#define KV6LD (LL * 1536)   // 9216

// ---------------- scratch ----------------
__device__ float  g_xe[NT * DD];
__device__ float  g_xd[NT * DD];
__device__ __half g_enc[NT * DD];
__device__ __half g_h[NT * DD];
__device__ __half g_qkv[NT * 3 * DD];
__device__ __half g_q[NT * DD];
__device__ __half g_kv6[(long)NT * KV6LD];
__device__ __half g_ao[NT * DD];
__device__ __half g_hid[NT * MM];
__device__ __half g_bias_e[HH * TT * TT];
__device__ __half g_bias_d[HH * TT * TT];
__device__ int    g_lut_e[1023];
__device__ int    g_lut_d[1023];
__device__ int    g_val_e[NT];
__device__ int    g_val_t[NT];
// transposed fp16 weights [N,K]
__device__ __half g_wA_e[LL * 3 * DD * DD];
__device__ __half g_wo_e[LL * DD * DD];
__device__ __half g_wA_s[LL * 3 * DD * DD];
__device__ __half g_wo_s[LL * DD * DD];
__device__ __half g_cqT [LL * DD * DD];
__device__ __half g_ckvT[LL * 2 * DD * DD];
__device__ __half g_coT [LL * DD * DD];
__device__ __half g_wiT_e [LL * DD * MM];
__device__ __half g_wmoT_e[LL * DD * MM];
__device__ __half g_wiT_d [LL * DD * MM];
__device__ __half g_wmoT_d[LL * DD * MM];
__device__ __half g_logT[(long)VV * DD];

// ---------------- helpers ----------------
__device__ __forceinline__ void cp16(unsigned dst, const void* src)
{ asm volatile("cp.async.cg.shared.global [%0], [%1], 16;\n" :: "r"(dst), "l"(src)); }
__device__ __forceinline__ void cp_commit() { asm volatile("cp.async.commit_group;\n"); }
__device__ __forceinline__ void cp_wait1()  { asm volatile("cp.async.wait_group 1;\n"); }
__device__ __forceinline__ void cp_wait2()  { asm volatile("cp.async.wait_group 2;\n"); }
__device__ __forceinline__ void cp_wait0()  { asm volatile("cp.async.wait_group 0;\n"); }

__device__ __forceinline__ unsigned su32(const void* p)
{ return (unsigned)__cvta_generic_to_shared(p); }

__device__ __forceinline__ void ldsm4(unsigned a_, unsigned* a)
{
    asm volatile("ldmatrix.sync.aligned.m8n8.x4.shared.b16 {%0,%1,%2,%3}, [%4];"
                 : "=r"(a[0]), "=r"(a[1]), "=r"(a[2]), "=r"(a[3]) : "r"(a_));
}
__device__ __forceinline__ void ldsm2(unsigned a_, unsigned* b)
{
    asm volatile("ldmatrix.sync.aligned.m8n8.x2.shared.b16 {%0,%1}, [%2];"
                 : "=r"(b[0]), "=r"(b[1]) : "r"(a_));
}
__device__ __forceinline__ void ldsm2t(unsigned a_, unsigned* b)
{
    asm volatile("ldmatrix.sync.aligned.m8n8.x2.trans.shared.b16 {%0,%1}, [%2];"
                 : "=r"(b[0]), "=r"(b[1]) : "r"(a_));
}
__device__ __forceinline__ void mma16(float* c, const unsigned* a, const unsigned* b)
{
    asm volatile("mma.sync.aligned.m16n8k16.row.col.f32.f16.f16.f32 "
                 "{%0,%1,%2,%3}, {%4,%5,%6,%7}, {%8,%9}, {%0,%1,%2,%3};"
                 : "+f"(c[0]), "+f"(c[1]), "+f"(c[2]), "+f"(c[3])
                 : "r"(a[0]), "r"(a[1]), "r"(a[2]), "r"(a[3]), "r"(b[0]), "r"(b[1]));
}

// ---------------- transposes ----------------
__global__ void transpose_b(const float* __restrict__ src, __half* __restrict__ dst,
                            int K, int N, long ss, long ds)
{
    __shared__ float t[32][33];
    const float* S = src + (long)blockIdx.z * ss;
    __half* D = dst + (long)blockIdx.z * ds;
    int k0 = blockIdx.y * 32, n0 = blockIdx.x * 32;
    int tx = threadIdx.x, ty = threadIdx.y;
#pragma unroll
    for (int i = 0; i < 32; i += 8)
        t[ty + i][tx] = S[(long)(k0 + ty + i) * N + n0 + tx];
    __syncthreads();
#pragma unroll
    for (int i = 0; i < 32; i += 8)
        D[(long)(n0 + ty + i) * K + k0 + tx] = __float2half_rn(t[tx][ty + i]);
}

struct P12 { const float* p[12]; };
struct D8  { __half* wAe; __half* woe; __half* wAs; __half* wos;
             __half* cqT; __half* ckvT; __half* coT; };

__global__ void transpose12(P12 srcs, D8 d)
{
    __shared__ float t[32][33];
    const int mat = blockIdx.z, layer = mat / 12, which = mat % 12;
    const float* S = srcs.p[which] + (long)layer * WSZ;
    __half* D;
    if (which < 3)       D = d.wAe + (long)layer * 3 * WSZ + (long)which * WSZ;
    else if (which == 3) D = d.woe + (long)layer * WSZ;
    else if (which < 7)  D = d.wAs + (long)layer * 3 * WSZ + (long)(which - 4) * WSZ;
    else if (which == 7) D = d.wos + (long)layer * WSZ;
    else if (which == 8) D = d.cqT + (long)layer * WSZ;
    else if (which < 11) D = d.ckvT + (long)layer * 2 * WSZ + (long)(which - 9) * WSZ;
    else                 D = d.coT + (long)layer * WSZ;
    int k0 = blockIdx.y * 32, n0 = blockIdx.x * 32;
    int tx = threadIdx.x, ty = threadIdx.y;
#pragma unroll
    for (int i = 0; i < 32; i += 8)
        t[ty + i][tx] = S[(long)(k0 + ty + i) * DD + n0 + tx];
    __syncthreads();
#pragma unroll
    for (int i = 0; i < 32; i += 8)
        D[(long)(n0 + ty + i) * DD + k0 + tx] = __float2half_rn(t[tx][ty + i]);
}

// ---------------- relpos bucket LUT + bias tables ----------------
__global__ void build_lut(int* __restrict__ lE, int* __restrict__ lD)
{
    int i = blockIdx.x * 256 + threadIdx.x;
    if (i >= 1023) return;
    int n = i - 511;
    {
        int ret = (n < 0) ? 16 : 0;
        int na = n < 0 ? -n : n;
        int bk;
        if (na < 8) bk = ret + na;
        else { int v = 8 + (int)(log((double)na / 8.0) / log(16.0) * 8.0); bk = ret + (v < 15 ? v : 15); }
        lE[i] = bk;
    }
    {
        int na = n > 0 ? n : 0;
        int bk;
        if (na < 16) bk = na;
        else { int v = 16 + (int)(log((double)na / 16.0) / log(8.0) * 16.0); bk = (v < 31 ? v : 31); }
        lD[i] = bk;
    }
}

__global__ void build_bias2(const float* __restrict__ relE, const int* __restrict__ lutE,
                            __half* __restrict__ biasE,
                            const float* __restrict__ relD, const int* __restrict__ lutD,
                            __half* __restrict__ biasD)
{
    const float* rel = blockIdx.y ? relD : relE;
    const int* lut   = blockIdx.y ? lutD : lutE;
    __half* bias     = blockIdx.y ? biasD : biasE;
    int idx = blockIdx.x * 256 + threadIdx.x;
    int q = idx / TT, s = idx % TT;
    int bk = lut[q - s + 511];
#pragma unroll
    for (int h = 0; h < HH; h++)
        bias[(long)h * TT * TT + idx] = __float2half_rn(rel[h * 32 + bk]);
}

// ---------------- tile loaders ----------------
__device__ __forceinline__ void load_tileH128(unsigned sbase, const __half* P,
                                              int row0, int k0, int ld, int tid)
{
#pragma unroll
    for (int j = 0; j < 8; j++) {
        int c = tid + 128 * j, m = c >> 3, kc = c & 7;
        cp16(sbase + ((m * 8 + (kc ^ (m & 7))) << 4),
             P + (long)(row0 + m) * ld + k0 + kc * 8);
    }
}
__device__ __forceinline__ void load_tileH256(unsigned sbase, const __half* P,
                                              int row0, int k0, int ld, int tid)
{
#pragma unroll
    for (int j = 0; j < 4; j++) {
        int c = tid + 256 * j, m = c >> 3, kc = c & 7;
        cp16(sbase + ((m * 8 + (kc ^ (m & 7))) << 4),
             P + (long)(row0 + m) * ld + k0 + kc * 8);
    }
}

// ---------------- fp16 NT GEMM, 4 warps / 64x64 warp tiles (big grids) ----------------
template<bool ACC, bool RELU, bool OUTH>
__global__ __launch_bounds__(128) void gemm_h(
    const __half* __restrict__ A, const __half* __restrict__ Bt, void* __restrict__ Cv,
    int K, int lda, int ldb, int ldc)
{
    extern __shared__ char smc[];
    const unsigned asb = su32(smc);
    const unsigned bsb = asb + 32768;
    constexpr int STG = 16384;

    const int tid = threadIdx.x, lane = tid & 31, warp = tid >> 5;
    const int mw = (warp & 1) * 64, nw = (warp >> 1) * 64;
    const int m0 = blockIdx.y * 128, n0 = blockIdx.x * 128;

    float acc[4][8][4];
#pragma unroll
    for (int i = 0; i < 4; i++)
#pragma unroll
        for (int j = 0; j < 8; j++)
#pragma unroll
            for (int q = 0; q < 4; q++) acc[i][j][q] = 0.f;

    const int nk = K >> 6;
    load_tileH128(asb, A, m0, 0, lda, tid);
    load_tileH128(bsb, Bt, n0, 0, ldb, tid);
    cp_commit();

    for (int kt = 0; kt < nk; kt++) {
        const int st = kt & 1;
        if (kt + 1 < nk) {
            load_tileH128(asb + (st ^ 1) * STG, A, m0, (kt + 1) << 6, lda, tid);
            load_tileH128(bsb + (st ^ 1) * STG, Bt, n0, (kt + 1) << 6, ldb, tid);
        }
        cp_commit();
        cp_wait1();
        __syncthreads();

        const unsigned ab = asb + st * STG;
        const unsigned bb = bsb + st * STG;
#pragma unroll
        for (int kk = 0; kk < 64; kk += 16) {
            unsigned a[4][4];
#pragma unroll
            for (int i = 0; i < 4; i++) {
                int r = mw + 16 * i + (lane & 15);
                int ch = (kk >> 3) + (lane >> 4);
                ldsm4(ab + ((r * 8 + (ch ^ (r & 7))) << 4), a[i]);
            }
            unsigned bf[8][2];
#pragma unroll
            for (int jj = 0; jj < 4; jj++) {
                unsigned t4[4];
                int r = nw + 16 * jj + ((lane >> 4) << 3) + (lane & 7);
                int ch = (kk >> 3) + ((lane >> 3) & 1);
                ldsm4(bb + ((r * 8 + (ch ^ (r & 7))) << 4), t4);
                bf[2 * jj][0] = t4[0]; bf[2 * jj][1] = t4[1];
                bf[2 * jj + 1][0] = t4[2]; bf[2 * jj + 1][1] = t4[3];
            }
#pragma unroll
            for (int i = 0; i < 4; i++)
#pragma unroll
                for (int j = 0; j < 8; j++) mma16(acc[i][j], a[i], bf[j]);
        }
        __syncthreads();
    }

#pragma unroll
    for (int i = 0; i < 4; i++) {
        int r = m0 + mw + 16 * i + (lane >> 2);
#pragma unroll
        for (int j = 0; j < 8; j++) {
            int cn = n0 + nw + 8 * j + ((lane & 3) << 1);
            float2 v0 = make_float2(acc[i][j][0], acc[i][j][1]);
            float2 v1 = make_float2(acc[i][j][2], acc[i][j][3]);
            if (RELU) {
                v0.x = fmaxf(v0.x, 0.f); v0.y = fmaxf(v0.y, 0.f);
                v1.x = fmaxf(v1.x, 0.f); v1.y = fmaxf(v1.y, 0.f);
            }
            if (OUTH) {
                __half* C = (__half*)Cv;
                *(__half2*)(C + (long)r * ldc + cn)       = __floats2half2_rn(v0.x, v0.y);
                *(__half2*)(C + (long)(r + 8) * ldc + cn) = __floats2half2_rn(v1.x, v1.y);
            } else {
                float* C = (float*)Cv;
                float2* p0 = (float2*)(C + (long)r * ldc + cn);
                float2* p1 = (float2*)(C + (long)(r + 8) * ldc + cn);
                if (ACC) {
                    float2 o0 = *p0, o1 = *p1;
                    v0.x += o0.x; v0.y += o0.y; v1.x += o1.x; v1.y += o1.y;
                }
                *p0 = v0; *p1 = v1;
            }
        }
    }
}

// ---- fp16 NT GEMM, 8 warps / 64x32 warp tiles, 3-stage pipeline (small grids) ----
template<bool ACC, bool RELU, bool OUTH>
__global__ __launch_bounds__(256) void gemm_h8(
    const __half* __restrict__ A, const __half* __restrict__ Bt, void* __restrict__ Cv,
    int K, int lda, int ldb, int ldc)
{
    extern __shared__ char smc[];
    const unsigned asb = su32(smc);
    const unsigned bsb = asb + 49152;      // A: 3 stages x 16KB
    constexpr int STG = 16384;

    const int tid = threadIdx.x, lane = tid & 31, warp = tid >> 5;
    const int mw = (warp & 1) * 64, nw = (warp >> 1) * 32;
    const int m0 = blockIdx.y * 128, n0 = blockIdx.x * 128;

    float acc[4][4][4];
#pragma unroll
    for (int i = 0; i < 4; i++)
#pragma unroll
        for (int j = 0; j < 4; j++)
#pragma unroll
            for (int q = 0; q < 4; q++) acc[i][j][q] = 0.f;

    const int nk = K >> 6;
    load_tileH256(asb, A, m0, 0, lda, tid);
    load_tileH256(bsb, Bt, n0, 0, ldb, tid);
    cp_commit();
    if (nk > 1) {
        load_tileH256(asb + STG, A, m0, 64, lda, tid);
        load_tileH256(bsb + STG, Bt, n0, 64, ldb, tid);
    }
    cp_commit();

    int st = 0;
    for (int kt = 0; kt < nk; kt++) {
        const int nxt = kt + 2;
        if (nxt < nk) {
            int sn = nxt % 3;
            load_tileH256(asb + sn * STG, A, m0, nxt << 6, lda, tid);
            load_tileH256(bsb + sn * STG, Bt, n0, nxt << 6, ldb, tid);
        }
        cp_commit();
        cp_wait2();
        __syncthreads();

        const unsigned ab = asb + st * STG;
        const unsigned bb = bsb + st * STG;
#pragma unroll
        for (int kk = 0; kk < 64; kk += 16) {
            unsigned a[4][4];
#pragma unroll
            for (int i = 0; i < 4; i++) {
                int r = mw + 16 * i + (lane & 15);
                int ch = (kk >> 3) + (lane >> 4);
                ldsm4(ab + ((r * 8 + (ch ^ (r & 7))) << 4), a[i]);
            }
            unsigned bf[4][2];
#pragma unroll
            for (int j = 0; j < 4; j++) {
                int r = nw + 8 * j + (lane & 7);
                int ch = (kk >> 3) + ((lane >> 3) & 1);
                ldsm2(bb + ((r * 8 + (ch ^ (r & 7))) << 4), bf[j]);
            }
#pragma unroll
            for (int i = 0; i < 4; i++)
#pragma unroll
                for (int j = 0; j < 4; j++) mma16(acc[i][j], a[i], bf[j]);
        }
        __syncthreads();
        st = (st == 2) ? 0 : st + 1;
    }

#pragma unroll
    for (int i = 0; i < 4; i++) {
        int r = m0 + mw + 16 * i + (lane >> 2);
#pragma unroll
        for (int j = 0; j < 4; j++) {
            int cn = n0 + nw + 8 * j + ((lane & 3) << 1);
            float2 v0 = make_float2(acc[i][j][0], acc[i][j][1]);
            float2 v1 = make_float2(acc[i][j][2], acc[i][j][3]);
            if (RELU) {
                v0.x = fmaxf(v0.x, 0.f); v0.y = fmaxf(v0.y, 0.f);
                v1.x = fmaxf(v1.x, 0.f); v1.y = fmaxf(v1.y, 0.f);
            }
            if (OUTH) {
                __half* C = (__half*)Cv;
                *(__half2*)(C + (long)r * ldc + cn)       = __floats2half2_rn(v0.x, v0.y);
                *(__half2*)(C + (long)(r + 8) * ldc + cn) = __floats2half2_rn(v1.x, v1.y);
            } else {
                float* C = (float*)Cv;
                float2* p0 = (float2*)(C + (long)r * ldc + cn);
                float2* p1 = (float2*)(C + (long)(r + 8) * ldc + cn);
                if (ACC) {
                    float2 o0 = *p0, o1 = *p1;
                    v0.x += o0.x; v0.y += o0.y; v1.x += o1.x; v1.y += o1.y;
                }
                *p0 = v0; *p1 = v1;
            }
        }
    }
}

// ================= fused flash attention (fp16 operands, half bias) =================
#define BQ   0
#define BKT  16384
#define BV   49152
#define BP   65536
#define BRED 98304
#define BVK  100352
#define BVQ  102400
#define FASMEM 104448

__global__ __launch_bounds__(256) void flash_attn(
    const __half* __restrict__ Q, int ldq,
    const __half* __restrict__ K, int ldk,
    const __half* __restrict__ V, int ldv,
    const __half* __restrict__ bias,
    const int* __restrict__ validQ, const int* __restrict__ validK,
    int causal, __half* __restrict__ O)
{
    extern __shared__ char smc[];
    float* smf = (float*)smc;
    int* smi = (int*)smc;
    __shared__ int s_anyinvalid;
    const unsigned sb = su32(smc);
    const int tid = threadIdx.x, lane = tid & 31, warp = tid >> 5;
    const int mw = (warp & 3) * 32;
    const int nwid = warp >> 2;
    const int nw = nwid * 64;
    const int nhd = nwid * 32;
    const int q0 = blockIdx.x * 128;
    const int z = blockIdx.y, b = z / HH, h = z % HH;
    const __half* Qp = Q + (long)b * TT * ldq + h * HDIM;
    const __half* Kp = K + (long)b * TT * ldk + h * HDIM;
    const __half* Vp = V + (long)b * TT * ldv + h * HDIM;
    const __half* biasH = bias ? bias + (long)h * TT * TT : nullptr;
    const int nt = TT / 128;

    auto loadQ = [&]() {
#pragma unroll
        for (int j = 0; j < 4; j++) {
            int c = tid + 256 * j, m = c >> 3, kc = c & 7;
            cp16(sb + BQ + ((m * 8 + (kc ^ (m & 7))) << 4),
                 Qp + (long)(q0 + m) * ldq + kc * 8);
        }
    };
    auto loadK = [&](int buf, int st) {
        int s0 = st * 128;
#pragma unroll
        for (int j = 0; j < 4; j++) {
            int c = tid + 256 * j, m = c >> 3, kc = c & 7;
            cp16(sb + BKT + buf * 16384 + ((m * 8 + (kc ^ (m & 7))) << 4),
                 Kp + (long)(s0 + m) * ldk + kc * 8);
        }
    };
    auto loadV = [&](int st) {
        int s0 = st * 128;
#pragma unroll
        for (int j = 0; j < 4; j++) {
            int c = tid + 256 * j, k = c >> 3, nc = c & 7;
            cp16(sb + BV + ((k * 8 + (nc ^ (k & 7))) << 4),
                 Vp + (long)(s0 + k) * ldv + nc * 8);
        }
    };

    loadQ(); loadK(0, 0); cp_commit();
    loadV(0); cp_commit();
    loadK(1, 1); cp_commit();

    smi[(BVK >> 2) + tid] = validK[b * TT + tid];
    smi[(BVK >> 2) + 256 + tid] = validK[b * TT + 256 + tid];
    smi[(BVQ >> 2) + tid] = validQ[b * TT + tid];
    smi[(BVQ >> 2) + 256 + tid] = validQ[b * TT + 256 + tid];
    if (tid == 0) s_anyinvalid = 0;

    cp_wait1();
    __syncthreads();

    int nt_eff = nt;
    if (causal) {
        if (tid < 128 && smi[(BVQ >> 2) + q0 + tid] == 0) s_anyinvalid = 1;
        __syncthreads();
        if (!s_anyinvalid) nt_eff = blockIdx.x + 1;
        __syncthreads();
    }

    float m_run[2][2], s_run[2][2], oacc[2][4][4];
#pragma unroll
    for (int i = 0; i < 2; i++)
#pragma unroll
        for (int rr = 0; rr < 2; rr++) { m_run[i][rr] = -3.0e38f; s_run[i][rr] = 0.f; }
#pragma unroll
    for (int i = 0; i < 2; i++)
#pragma unroll
        for (int j = 0; j < 4; j++)
#pragma unroll
            for (int q = 0; q < 4; q++) oacc[i][j][q] = 0.f;

    for (int t = 0; t < nt_eff; t++) {
        if (t >= 1) {
            loadV(t); cp_commit();
            if (t + 1 < nt_eff) { loadK((t + 1) & 1, t + 1); cp_commit(); }
        }
        const int s0 = t * 128;

        float acc[2][8][4];
#pragma unroll
        for (int i = 0; i < 2; i++)
#pragma unroll
            for (int j = 0; j < 8; j++)
#pragma unroll
                for (int q = 0; q < 4; q++) acc[i][j][q] = 0.f;

        const unsigned kb = sb + BKT + (t & 1) * 16384;
#pragma unroll
        for (int kk = 0; kk < 64; kk += 16) {
            unsigned a[2][4];
#pragma unroll
            for (int i = 0; i < 2; i++) {
                int r = mw + 16 * i + (lane & 15);
                int ch = (kk >> 3) + (lane >> 4);
                ldsm4(sb + BQ + ((r * 8 + (ch ^ (r & 7))) << 4), a[i]);
            }
            unsigned bf[8][2];
#pragma unroll
            for (int j = 0; j < 8; j++) {
                int r = nw + 8 * j + (lane & 7);
                int ch = (kk >> 3) + ((lane >> 3) & 1);
                ldsm2(kb + ((r * 8 + (ch ^ (r & 7))) << 4), bf[j]);
            }
#pragma unroll
            for (int i = 0; i < 2; i++)
#pragma unroll
                for (int j = 0; j < 8; j++) mma16(acc[i][j], a[i], bf[j]);
        }

        // bias + mask
#pragma unroll
        for (int i = 0; i < 2; i++)
#pragma unroll
            for (int rr = 0; rr < 2; rr++) {
                int Rl = mw + 16 * i + 8 * rr + (lane >> 2);
                int q = q0 + Rl;
                int vq = smi[(BVQ >> 2) + q];
#pragma unroll
                for (int j = 0; j < 8; j++) {
                    int Cl = nw + 8 * j + 2 * (lane & 3);
                    int s = s0 + Cl;
                    float b0 = 0.f, b1 = 0.f;
                    if (biasH) {
                        __half2 bb = *(const __half2*)(biasH + (long)q * TT + s);
                        b0 = __half2float(__low2half(bb));
                        b1 = __half2float(__high2half(bb));
                    }
                    int2 vk = *(const int2*)(smi + (BVK >> 2) + s);
                    float v0 = acc[i][j][2 * rr + 0] + b0;
                    float v1 = acc[i][j][2 * rr + 1] + b1;
                    bool m0 = vq && vk.x && (!causal || s <= q);
                    bool m1 = vq && vk.y && (!causal || s + 1 <= q);
                    acc[i][j][2 * rr + 0] = m0 ? v0 : NEGINF;
                    acc[i][j][2 * rr + 1] = m1 ? v1 : NEGINF;
                }
            }

        // row max
        float mp[2][2];
#pragma unroll
        for (int i = 0; i < 2; i++)
#pragma unroll
            for (int rr = 0; rr < 2; rr++) {
                float m = -3.4e38f;
#pragma unroll
                for (int j = 0; j < 8; j++)
                    m = fmaxf(m, fmaxf(acc[i][j][2 * rr], acc[i][j][2 * rr + 1]));
                mp[i][rr] = m;
            }
#pragma unroll
        for (int o = 1; o <= 2; o <<= 1)
#pragma unroll
            for (int i = 0; i < 2; i++)
#pragma unroll
                for (int rr = 0; rr < 2; rr++)
                    mp[i][rr] = fmaxf(mp[i][rr], __shfl_xor_sync(0xffffffffu, mp[i][rr], o));
        if ((lane & 3) == 0) {
#pragma unroll
            for (int i = 0; i < 2; i++)
#pragma unroll
                for (int rr = 0; rr < 2; rr++) {
                    int Rl = mw + 16 * i + 8 * rr + (lane >> 2);
                    smf[(BRED >> 2) + Rl * 2 + nwid] = mp[i][rr];
                }
        }
        __syncthreads();

        float mnew[2][2], scl[2][2];
#pragma unroll
        for (int i = 0; i < 2; i++)
#pragma unroll
            for (int rr = 0; rr < 2; rr++) {
                int Rl = mw + 16 * i + 8 * rr + (lane >> 2);
                float mt = fmaxf(smf[(BRED >> 2) + Rl * 2], smf[(BRED >> 2) + Rl * 2 + 1]);
                float mn = fmaxf(m_run[i][rr], mt);
                scl[i][rr] = __expf(m_run[i][rr] - mn);
                m_run[i][rr] = mn;
                mnew[i][rr] = mn;
            }

        // p = exp(s-m), stage P (fp16), partial sums
        float sp[2][2] = {{0.f, 0.f}, {0.f, 0.f}};
#pragma unroll
        for (int i = 0; i < 2; i++)
#pragma unroll
            for (int rr = 0; rr < 2; rr++) {
                int Rl = mw + 16 * i + 8 * rr + (lane >> 2);
#pragma unroll
                for (int j = 0; j < 8; j++) {
                    float p0 = __expf(acc[i][j][2 * rr + 0] - mnew[i][rr]);
                    float p1 = __expf(acc[i][j][2 * rr + 1] - mnew[i][rr]);
                    sp[i][rr] += p0 + p1;
                    int Cl = nw + 8 * j + 2 * (lane & 3);
                    int nc = Cl >> 3;
                    *(__half2*)(smc + BP + Rl * 256 + ((nc ^ (Rl & 7)) << 4) + (Cl & 7) * 2) =
                        __floats2half2_rn(p0, p1);
                }
            }
#pragma unroll
        for (int o = 1; o <= 2; o <<= 1)
#pragma unroll
            for (int i = 0; i < 2; i++)
#pragma unroll
                for (int rr = 0; rr < 2; rr++)
                    sp[i][rr] += __shfl_xor_sync(0xffffffffu, sp[i][rr], o);
        if ((lane & 3) == 0) {
#pragma unroll
            for (int i = 0; i < 2; i++)
#pragma unroll
                for (int rr = 0; rr < 2; rr++) {
                    int Rl = mw + 16 * i + 8 * rr + (lane >> 2);
                    smf[(BRED >> 2) + 256 + Rl * 2 + nwid] = sp[i][rr];
                }
        }
        if (t + 1 < nt_eff) cp_wait1(); else cp_wait0();
        __syncthreads();

#pragma unroll
        for (int i = 0; i < 2; i++)
#pragma unroll
            for (int rr = 0; rr < 2; rr++) {
                int Rl = mw + 16 * i + 8 * rr + (lane >> 2);
                float st = smf[(BRED >> 2) + 256 + Rl * 2] + smf[(BRED >> 2) + 256 + Rl * 2 + 1];
                s_run[i][rr] = s_run[i][rr] * scl[i][rr] + st;
            }
#pragma unroll
        for (int i = 0; i < 2; i++)
#pragma unroll
            for (int j = 0; j < 4; j++) {
                oacc[i][j][0] *= scl[i][0]; oacc[i][j][1] *= scl[i][0];
                oacc[i][j][2] *= scl[i][1]; oacc[i][j][3] *= scl[i][1];
            }

        // PV
#pragma unroll
        for (int kk = 0; kk < 128; kk += 16) {
            unsigned a[2][4];
#pragma unroll
            for (int i = 0; i < 2; i++) {
                int r = mw + 16 * i + (lane & 15);
                int ch = (kk >> 3) + (lane >> 4);
                ldsm4(sb + BP + ((r * 16 + (ch ^ (r & 7))) << 4), a[i]);
            }
            unsigned bf[4][2];
#pragma unroll
            for (int j = 0; j < 4; j++) {
                int n0c = (nhd + 8 * j) >> 3;
                int r = kk + (lane & 7) + ((lane >> 3) & 1) * 8;
                ldsm2t(sb + BV + ((r * 8 + (n0c ^ (r & 7))) << 4), bf[j]);
            }
#pragma unroll
            for (int i = 0; i < 2; i++)
#pragma unroll
                for (int j = 0; j < 4; j++) mma16(oacc[i][j], a[i], bf[j]);
        }

        if (t + 1 < nt_eff) { cp_wait0(); __syncthreads(); }
    }

    __half* Op = O + (long)b * TT * DD + h * HDIM;
#pragma unroll
    for (int i = 0; i < 2; i++)
#pragma unroll
        for (int rr = 0; rr < 2; rr++) {
            int Rl = mw + 16 * i + 8 * rr + (lane >> 2);
            float inv = 1.0f / s_run[i][rr];
#pragma unroll
            for (int j = 0; j < 4; j++) {
                int cn = nhd + 8 * j + 2 * (lane & 3);
                *(__half2*)(Op + (long)(q0 + Rl) * DD + cn) =
                    __floats2half2_rn(oacc[i][j][2 * rr + 0] * inv,
                                      oacc[i][j][2 * rr + 1] * inv);
            }
        }
}

// ---------------- elementwise ----------------
// warp-per-row rmsnorm: 8 warps/block, 1 row/warp, no block sync
__global__ __launch_bounds__(256) void rmsnorm_k(const float* __restrict__ X,
                                                 const float* __restrict__ scale,
                                                 __half* __restrict__ O)
{
    const int warp = threadIdx.x >> 5, lane = threadIdx.x & 31;
    const int row = blockIdx.x * 8 + warp;
    const float4* xp = (const float4*)(X + (long)row * DD);
    const float4* sp = (const float4*)scale;
    float4 v[6];
    float s = 0.f;
#pragma unroll
    for (int i = 0; i < 6; i++) {
        v[i] = xp[i * 32 + lane];
        s += v[i].x * v[i].x + v[i].y * v[i].y + v[i].z * v[i].z + v[i].w * v[i].w;
    }
#pragma unroll
    for (int o = 16; o > 0; o >>= 1) s += __shfl_xor_sync(0xffffffffu, s, o);
    const float r = 1.0f / sqrtf(s / (float)DD + 1e-6f);
    __half2* op = (__half2*)(O + (long)row * DD);
#pragma unroll
    for (int i = 0; i < 6; i++) {
        float4 sc = sp[i * 32 + lane];
        op[(i * 32 + lane) * 2]     = __floats2half2_rn(v[i].x * r * sc.x, v[i].y * r * sc.y);
        op[(i * 32 + lane) * 2 + 1] = __floats2half2_rn(v[i].z * r * sc.z, v[i].w * r * sc.w);
    }
}

__global__ void embed2_k(const int* __restrict__ tokE, const int* __restrict__ tokD,
                         const float* __restrict__ emb,
                         float* __restrict__ Oe, float* __restrict__ Od)
{
    int t = blockIdx.x;
    const int* tok = (t < NT) ? tokE : tokD;
    float* O = (t < NT) ? Oe : Od;
    int tt = (t < NT) ? t : t - NT;
    const float* e = emb + (size_t)tok[tt] * DD;
    for (int d = threadIdx.x; d < DD; d += 256) O[(size_t)tt * DD + d] = e[d];
}

__global__ void valid2_k(const int* __restrict__ tokA, const int* __restrict__ tokB,
                         int* __restrict__ vA, int* __restrict__ vB)
{
    int i = blockIdx.x * blockDim.x + threadIdx.x;
    if (i < NT) vA[i] = tokA[i] > 0 ? 1 : 0;
    else { int j = i - NT; vB[j] = tokB[j] > 0 ? 1 : 0; }
}

// ---------------- host ----------------
#define SMEM_G 65536
#define SMEM_G8 98304

static void set_attrs()
{
    cudaFuncSetAttribute(gemm_h<false, false, true >, cudaFuncAttributeMaxDynamicSharedMemorySize, SMEM_G);
    cudaFuncSetAttribute(gemm_h<false, true,  true >, cudaFuncAttributeMaxDynamicSharedMemorySize, SMEM_G);
    cudaFuncSetAttribute(gemm_h<false, false, false>, cudaFuncAttributeMaxDynamicSharedMemorySize, SMEM_G);
    cudaFuncSetAttribute(gemm_h8<true,  false, false>, cudaFuncAttributeMaxDynamicSharedMemorySize, SMEM_G8);
    cudaFuncSetAttribute(gemm_h8<false, false, true >, cudaFuncAttributeMaxDynamicSharedMemorySize, SMEM_G8);
    cudaFuncSetAttribute(flash_attn, cudaFuncAttributeMaxDynamicSharedMemorySize, FASMEM);
}

extern "C" void kernel_launch(void* const* d_in, const int* in_sizes, int n_in,
                              void* d_out, int out_size)
{
    const float* emb      = (const float*)d_in[0];
    const float* rel_enc  = (const float*)d_in[1];
    const float* rel_dec  = (const float*)d_in[2];
    const float* enc_ln1  = (const float*)d_in[3];
    const float* enc_wq   = (const float*)d_in[4];
    const float* enc_wk   = (const float*)d_in[5];
    const float* enc_wv   = (const float*)d_in[6];
    const float* enc_wo   = (const float*)d_in[7];
    const float* enc_ln2  = (const float*)d_in[8];
    const float* enc_wi   = (const float*)d_in[9];
    const float* enc_wmo  = (const float*)d_in[10];
    const float* enc_norm = (const float*)d_in[11];
    const float* dec_ln1  = (const float*)d_in[12];
    const float* dec_sq   = (const float*)d_in[13];
    const float* dec_sk   = (const float*)d_in[14];
    const float* dec_sv   = (const float*)d_in[15];
    const float* dec_so   = (const float*)d_in[16];
    const float* dec_ln2  = (const float*)d_in[17];
    const float* dec_cq   = (const float*)d_in[18];
    const float* dec_ck   = (const float*)d_in[19];
    const float* dec_cv   = (const float*)d_in[20];
    const float* dec_co   = (const float*)d_in[21];
    const float* dec_ln3  = (const float*)d_in[22];
    const float* dec_wi   = (const float*)d_in[23];
    const float* dec_wmo  = (const float*)d_in[24];
    const float* dec_norm = (const float*)d_in[25];
    const float* logits_w = (const float*)d_in[26];
    const int* enc_tok    = (const int*)d_in[27];
    const int* dec_in_tok = (const int*)d_in[28];
    const int* dec_tgt    = (const int*)d_in[29];

    float *xe, *xd;
    __half *enc, *h, *qkv, *q, *kv6, *ao, *hid, *be, *bd;
    __half *wAe, *woe, *wAs, *wos, *cqT, *ckvT, *coT, *wie, *wmoe, *wid_, *wmod, *logT;
    int *ve, *vt, *lutE, *lutD;
    cudaGetSymbolAddress((void**)&xe, g_xe);     cudaGetSymbolAddress((void**)&xd, g_xd);
    cudaGetSymbolAddress((void**)&enc, g_enc);   cudaGetSymbolAddress((void**)&h, g_h);
    cudaGetSymbolAddress((void**)&qkv, g_qkv);   cudaGetSymbolAddress((void**)&q, g_q);
    cudaGetSymbolAddress((void**)&kv6, g_kv6);   cudaGetSymbolAddress((void**)&ao, g_ao);
    cudaGetSymbolAddress((void**)&hid, g_hid);
    cudaGetSymbolAddress((void**)&be, g_bias_e); cudaGetSymbolAddress((void**)&bd, g_bias_d);
    cudaGetSymbolAddress((void**)&ve, g_val_e);  cudaGetSymbolAddress((void**)&vt, g_val_t);
    cudaGetSymbolAddress((void**)&lutE, g_lut_e); cudaGetSymbolAddress((void**)&lutD, g_lut_d);
    cudaGetSymbolAddress((void**)&wAe, g_wA_e);  cudaGetSymbolAddress((void**)&woe, g_wo_e);
    cudaGetSymbolAddress((void**)&wAs, g_wA_s);  cudaGetSymbolAddress((void**)&wos, g_wo_s);
    cudaGetSymbolAddress((void**)&cqT, g_cqT);   cudaGetSymbolAddress((void**)&ckvT, g_ckvT);
    cudaGetSymbolAddress((void**)&coT, g_coT);   cudaGetSymbolAddress((void**)&wie, g_wiT_e);
    cudaGetSymbolAddress((void**)&wmoe, g_wmoT_e); cudaGetSymbolAddress((void**)&wid_, g_wiT_d);
    cudaGetSymbolAddress((void**)&wmod, g_wmoT_d); cudaGetSymbolAddress((void**)&logT, g_logT);

    set_attrs();

    valid2_k<<<(2 * NT) / 256, 256>>>(enc_tok, dec_tgt, ve, vt);
    build_lut<<<4, 256>>>(lutE, lutD);
    build_bias2<<<dim3((TT * TT) / 256, 2), 256>>>(rel_enc, lutE, be, rel_dec, lutD, bd);
    embed2_k<<<2 * NT, 256>>>(enc_tok, dec_in_tok, emb, xe, xd);

    {
        P12 s;
        s.p[0] = enc_wq; s.p[1] = enc_wk; s.p[2] = enc_wv; s.p[3] = enc_wo;
        s.p[4] = dec_sq; s.p[5] = dec_sk; s.p[6] = dec_sv; s.p[7] = dec_so;
        s.p[8] = dec_cq; s.p[9] = dec_ck; s.p[10] = dec_cv; s.p[11] = dec_co;
        D8 d; d.wAe = wAe; d.woe = woe; d.wAs = wAs; d.wos = wos;
        d.cqT = cqT; d.ckvT = ckvT; d.coT = coT;
        transpose12<<<dim3(24, 24, 72), dim3(32, 8)>>>(s, d);
    }
    transpose_b<<<dim3(MM / 32, DD / 32, 6), dim3(32, 8)>>>(enc_wi,  wie,  DD, MM, DMM, DMM);
    transpose_b<<<dim3(DD / 32, MM / 32, 6), dim3(32, 8)>>>(enc_wmo, wmoe, MM, DD, DMM, DMM);
    transpose_b<<<dim3(MM / 32, DD / 32, 6), dim3(32, 8)>>>(dec_wi,  wid_, DD, MM, DMM, DMM);
    transpose_b<<<dim3(DD / 32, MM / 32, 6), dim3(32, 8)>>>(dec_wmo, wmod, MM, DD, DMM, DMM);
    transpose_b<<<dim3(VV / 32, DD / 32, 1), dim3(32, 8)>>>(logits_w, logT, DD, VV, 0, 0);

    const long QS = 3 * WSZ;

    auto self_attn = [&](const __half* hin, const __half* wqkvT, const __half* woT, float* x,
                         const __half* bias, const int* vQ, const int* vK, int causal) {
        gemm_h<false, false, true><<<dim3(18, 16), 128, SMEM_G>>>(hin, wqkvT, qkv, DD, DD, DD, 2304);
        flash_attn<<<dim3(4, 48), 256, FASMEM>>>(qkv, 2304, qkv + 768, 2304, qkv + 1536, 2304,
                                                 bias, vQ, vK, causal, ao);
        gemm_h8<true, false, false><<<dim3(6, 16), 256, SMEM_G8>>>(ao, woT, x, DD, DD, DD, DD);
    };
    auto mlp = [&](const __half* hin, const __half* wiT, const __half* wmoT, float* x) {
        gemm_h<false, true, true><<<dim3(24, 16), 128, SMEM_G>>>(hin, wiT, hid, DD, DD, DD, MM);
        gemm_h8<true, false, false><<<dim3(6, 16), 256, SMEM_G8>>>(hid, wmoT, x, MM, MM, MM, DD);
    };

    // -------- encoder --------
    for (int l = 0; l < LL; l++) {
        rmsnorm_k<<<NT / 8, 256>>>(xe, enc_ln1 + (size_t)l * DD, h);
        self_attn(h, wAe + l * QS, woe + l * WSZ, xe, be, ve, ve, 0);
        rmsnorm_k<<<NT / 8, 256>>>(xe, enc_ln2 + (size_t)l * DD, h);
        mlp(h, wie + l * DMM, wmoe + l * DMM, xe);
    }
    rmsnorm_k<<<NT / 8, 256>>>(xe, enc_norm, enc);

    // -------- decoder --------
    gemm_h<false, false, true><<<dim3(KV6LD / 128, 16), 128, SMEM_G>>>(
        enc, ckvT, kv6, DD, DD, DD, KV6LD);

    for (int l = 0; l < LL; l++) {
        rmsnorm_k<<<NT / 8, 256>>>(xd, dec_ln1 + (size_t)l * DD, h);
        self_attn(h, wAs + l * QS, wos + l * WSZ, xd, bd, vt, vt, 1);
        rmsnorm_k<<<NT / 8, 256>>>(xd, dec_ln2 + (size_t)l * DD, h);
        gemm_h8<false, false, true><<<dim3(6, 16), 256, SMEM_G8>>>(h, cqT + l * WSZ, q, DD, DD, DD, DD);
        flash_attn<<<dim3(4, 48), 256, FASMEM>>>(q, DD,
                                                 kv6 + (long)l * 1536, KV6LD,
                                                 kv6 + (long)l * 1536 + 768, KV6LD,
                                                 nullptr, vt, ve, 0, ao);
        gemm_h8<true, false, false><<<dim3(6, 16), 256, SMEM_G8>>>(ao, coT + l * WSZ, xd, DD, DD, DD, DD);
        rmsnorm_k<<<NT / 8, 256>>>(xd, dec_ln3 + (size_t)l * DD, h);
        mlp(h, wid_ + l * DMM, wmod + l * DMM, xd);
    }
    rmsnorm_k<<<NT / 8, 256>>>(xd, dec_norm, h);

    // -------- logits --------
    gemm_h<false, false, false><<<dim3(251, 16), 128, SMEM_G>>>(h, logT, (float*)d_out, DD, DD, DD, VV);
}